// round 14
// baseline (speedup 1.0000x reference)
#include <cuda_runtime.h>
#include <cuda_bf16.h>
#include <math.h>
#include <stdint.h>

// Problem constants
#define BB 4
#define NN 6
#define FDIM 256
#define DDIM 128
#define HH 64
#define WW 120
#define PP (HH*WW)          // 7680
#define BN (BB*NN)          // 24
#define IMG_H 480.0f
#define IMG_W 960.0f

// Scratch (device globals — no runtime allocation allowed)
__device__ float g_val[(size_t)BN * PP * DDIM];   // (bn, p, d)  94.4 MB
__device__ float g_z[(size_t)BB * PP * DDIM];     // (b, p, d)   15.7 MB
__device__ float g_Hm[BN * 9];
__device__ float g_bnscale[FDIM];
__device__ float g_bnshift[FDIM];
// Prepacked split-bf16 weights
__device__ uint32_t g_wch[128 * 128];  // conv_w hi pairs [d][kpair]
__device__ uint32_t g_wcl[128 * 128];  // conv_w lo pairs
__device__ uint2 g_w1p[256 * 64];      // W1^T  [n=256][kpair=64]
__device__ uint2 g_w2p[128 * 128];     // W2^T  [n=128][kpair=128]

// ===========================================================================
// helpers
// ===========================================================================
__device__ __forceinline__ uint32_t smem_u32(const void* p) {
    uint32_t a;
    asm("{ .reg .u64 t; cvta.to.shared.u64 t, %1; cvt.u32.u64 %0, t; }"
        : "=r"(a) : "l"(p));
    return a;
}
__device__ __forceinline__ void ldsm_x4(uint32_t* r, uint32_t addr) {
    asm volatile("ldmatrix.sync.aligned.m8n8.x4.shared.b16 {%0,%1,%2,%3}, [%4];"
        : "=r"(r[0]), "=r"(r[1]), "=r"(r[2]), "=r"(r[3]) : "r"(addr));
}
__device__ __forceinline__ void mma_bf16(float* c, const uint32_t* a,
                                         uint32_t b0, uint32_t b1) {
    asm volatile(
        "mma.sync.aligned.m16n8k16.row.col.f32.bf16.bf16.f32 "
        "{%0,%1,%2,%3}, {%4,%5,%6,%7}, {%8,%9}, {%0,%1,%2,%3};"
        : "+f"(c[0]), "+f"(c[1]), "+f"(c[2]), "+f"(c[3])
        : "r"(a[0]), "r"(a[1]), "r"(a[2]), "r"(a[3]), "r"(b0), "r"(b1));
}
__device__ __forceinline__ void cp_async16(uint32_t smem_addr, const void* gptr) {
    asm volatile("cp.async.ca.shared.global [%0], [%1], 16;"
        :: "r"(smem_addr), "l"(gptr) : "memory");
}
#define NB_SYNC(id)   asm volatile("bar.sync %0, 384;"   :: "r"(id) : "memory")
#define NB_ARRIVE(id) asm volatile("bar.arrive %0, 384;" :: "r"(id) : "memory")
__device__ __forceinline__ uint32_t pack_bf16x2(__nv_bfloat16 lo, __nv_bfloat16 hi) {
    return ((uint32_t)__bfloat16_as_ushort(hi) << 16) | __bfloat16_as_ushort(lo);
}
__device__ __forceinline__ uint2 split_pack(float a, float b) {
    __nv_bfloat16 ha = __float2bfloat16(a), hb = __float2bfloat16(b);
    __nv_bfloat16 la = __float2bfloat16(a - __bfloat162float(ha));
    __nv_bfloat16 lb = __float2bfloat16(b - __bfloat162float(hb));
    return make_uint2(pack_bf16x2(ha, hb), pack_bf16x2(la, lb));
}
__device__ __forceinline__ float bflo_f(uint32_t u) { return __uint_as_float(u << 16); }
__device__ __forceinline__ float bfhi_f(uint32_t u) { return __uint_as_float(u & 0xffff0000u); }
__device__ __forceinline__ float geluf(float h) {
    return 0.5f * h * (1.f + erff(h * 0.70710678118654752f));
}
__device__ __forceinline__ float wred(float v) {
    #pragma unroll
    for (int o = 16; o; o >>= 1) v += __shfl_xor_sync(0xffffffffu, v, o);
    return v;
}

// ---------------------------------------------------------------------------
// K0: homographies + BN scale/shift
// ---------------------------------------------------------------------------
__global__ void k0_prep(const float* __restrict__ I_src,
                        const float* __restrict__ I_tar_inv,
                        const float* __restrict__ E,
                        const float* __restrict__ disp,
                        const float* __restrict__ nvec,
                        const float* __restrict__ bng,
                        const float* __restrict__ bnb,
                        const float* __restrict__ bnm,
                        const float* __restrict__ bnv)
{
    int t = threadIdx.x;
    if (t < FDIM) {
        float sc = bng[t] * rsqrtf(bnv[t] + 1e-5f);
        g_bnscale[t] = sc;
        g_bnshift[t] = bnb[t] - bnm[t] * sc;
    }
    if (t < BN) {
        int b = t / NN;
        float dis = disp[0];
        const float* Eb = E + t * 16;
        const float* Ks = I_src + t * 9;
        const float* Kt = I_tar_inv + b * 9;
        float nv0 = nvec[b*3+0], nv1 = nvec[b*3+1], nv2 = nvec[b*3+2];
        float A[9];
        #pragma unroll
        for (int i = 0; i < 3; i++) {
            float Ti = Eb[i*4+3] / dis;
            A[i*3+0] = Eb[i*4+0] - Ti * nv0;
            A[i*3+1] = Eb[i*4+1] - Ti * nv1;
            A[i*3+2] = Eb[i*4+2] - Ti * nv2;
        }
        float M[9];
        #pragma unroll
        for (int i = 0; i < 3; i++)
            #pragma unroll
            for (int j = 0; j < 3; j++)
                M[i*3+j] = Ks[i*3+0]*A[0*3+j] + Ks[i*3+1]*A[1*3+j] + Ks[i*3+2]*A[2*3+j];
        #pragma unroll
        for (int i = 0; i < 3; i++)
            #pragma unroll
            for (int j = 0; j < 3; j++)
                g_Hm[t*9 + i*3+j] = M[i*3+0]*Kt[0*3+j] + M[i*3+1]*Kt[1*3+j] + M[i*3+2]*Kt[2*3+j];
    }
}

// ---------------------------------------------------------------------------
// K0b: pack weights to split-bf16 transposed layouts
// ---------------------------------------------------------------------------
__global__ void k0b_pack(const float* __restrict__ Wc,
                         const float* __restrict__ W1,
                         const float* __restrict__ W2)
{
    int i = blockIdx.x * 256 + threadIdx.x;   // 0..16383
    {
        int d = i >> 7, fp = i & 127;
        uint2 p = split_pack(Wc[d*256 + fp*2], Wc[d*256 + fp*2 + 1]);
        g_wch[i] = p.x;
        g_wcl[i] = p.y;
    }
    {
        int d = i >> 7, kp = i & 127;
        g_w2p[i] = split_pack(W2[(kp*2)*128 + d], W2[(kp*2+1)*128 + d]);
    }
    {
        int j = i >> 6, kp = i & 63;
        g_w1p[i] = split_pack(W1[(kp*2)*256 + j], W1[(kp*2+1)*256 + j]);
    }
}

// ---------------------------------------------------------------------------
// K1 (HMMA, warp-specialized producer/consumer):
// val[bn][p][d] = sum_f W[d][f]*relu(bn(feat))
// 384 threads: warps 0-7 consumers (MMA), warps 8-11 producers (X + W).
// 2-stage buffers: X s @ s*32768 (hi) / +16384 (lo); W s @ 65536+s*32768.
// Barriers (count 384): FULL_s = 1+s (prod arrive, cons sync),
//                       EMPTY_s = 3+s (cons arrive, prod sync).
// ---------------------------------------------------------------------------
#define K1_SMEM 131072

__global__ void __launch_bounds__(384)
k1_conv_tc(const float* __restrict__ feat)
{
    extern __shared__ char smem[];
    const uint32_t sb = smem_u32(smem);
    const int bn = blockIdx.y;
    const int p0 = blockIdx.x * 128;
    const int t  = threadIdx.x;
    const int wid = t >> 5, lane = t & 31;

    const float* fb = feat + (size_t)bn * FDIM * PP + p0;

    if (wid >= 8) {
        // ================= PRODUCER (128 threads) =================
        const int pt = t - 256;     // 0..127
        const int pl = pt;          // pixel row owned by this thread
        for (int c = 0; c < 4; c++) {
            const int s = c & 1;
            if (c >= 2) NB_SYNC(3 + s);           // wait EMPTY_s
            // W chunk c via cp.async into stage s
            const uint32_t wb = sb + 65536 + (uint32_t)s * 32768;
            #pragma unroll
            for (int i = 0; i < 8; i++) {
                int idx = pt + i * 128;           // 16B-unit 0..1023
                int kq = idx & 7, dl = idx >> 3;
                uint32_t off = (uint32_t)dl * 128 + (((uint32_t)kq * 16) ^ ((dl & 7) << 4));
                cp_async16(wb + off,         g_wch + dl * 128 + c * 32 + kq * 4);
                cp_async16(wb + 16384 + off, g_wcl + dl * 128 + c * 32 + kq * 4);
            }
            asm volatile("cp.async.commit_group;" ::: "memory");
            // X chunk c: LDG -> BN+relu -> split -> STS into stage s
            {
                char* xd = smem + (size_t)s * 32768;
                const int f0 = c * 64;
                #pragma unroll
                for (int i = 0; i < 32; i++) {
                    int f = f0 + 2 * i;
                    float v0 = fb[(size_t)f       * PP + pl];
                    float v1 = fb[(size_t)(f + 1) * PP + pl];
                    v0 = fmaxf(fmaf(v0, g_bnscale[f],   g_bnshift[f]),   0.f);
                    v1 = fmaxf(fmaf(v1, g_bnscale[f+1], g_bnshift[f+1]), 0.f);
                    uint2 p = split_pack(v0, v1);
                    uint32_t off = (uint32_t)pl * 128 + (((uint32_t)i * 4) ^ ((pl & 7) << 4));
                    *(uint32_t*)(xd + off)         = p.x;
                    *(uint32_t*)(xd + 16384 + off) = p.y;
                }
            }
            asm volatile("cp.async.wait_group 0;" ::: "memory");
            NB_ARRIVE(1 + s);                     // signal FULL_s
        }
        return;
    }

    // ================= CONSUMER (256 threads, 8 warps) =================
    const int wm = wid & 3;    // M quarter
    const int wn = wid >> 2;   // N half

    float acc[2][8][4];
    #pragma unroll
    for (int mi = 0; mi < 2; mi++)
        #pragma unroll
        for (int nt = 0; nt < 8; nt++)
            #pragma unroll
            for (int j = 0; j < 4; j++) acc[mi][nt][j] = 0.f;

    for (int c = 0; c < 4; c++) {
        const int s = c & 1;
        NB_SYNC(1 + s);                           // wait FULL_s
        const uint32_t xbase = sb + (uint32_t)s * 32768;
        const uint32_t wbase = sb + 65536 + (uint32_t)s * 32768;

        #pragma unroll
        for (int ks = 0; ks < 4; ks++) {
            const uint32_t kb = (uint32_t)ks * 32;
            uint32_t ah[2][4], al[2][4];
            #pragma unroll
            for (int mi = 0; mi < 2; mi++) {
                uint32_t row = (uint32_t)(wm * 32 + mi * 16 + (lane & 15));
                uint32_t kby = kb + ((lane >> 4) << 4);
                uint32_t off = row * 128 + (kby ^ ((row & 7) << 4));
                ldsm_x4(ah[mi], xbase + off);
                ldsm_x4(al[mi], xbase + 16384 + off);
            }
            uint32_t bh[4][4], bl[4][4];
            #pragma unroll
            for (int bj = 0; bj < 4; bj++) {
                uint32_t rown = (uint32_t)(wn * 64 + bj * 16 + (lane & 7) + ((lane >> 4) << 3));
                uint32_t kby  = kb + (((lane >> 3) & 1) << 4);
                uint32_t off  = rown * 128 + (kby ^ ((rown & 7) << 4));
                ldsm_x4(bh[bj], wbase + off);
                ldsm_x4(bl[bj], wbase + 16384 + off);
            }
            // term-major: hh -> hl -> lh (16 independent MMAs between acc reuse)
            #pragma unroll
            for (int bj = 0; bj < 4; bj++)
                #pragma unroll
                for (int mi = 0; mi < 2; mi++) {
                    mma_bf16(acc[mi][bj*2+0], ah[mi], bh[bj][0], bh[bj][1]);
                    mma_bf16(acc[mi][bj*2+1], ah[mi], bh[bj][2], bh[bj][3]);
                }
            #pragma unroll
            for (int bj = 0; bj < 4; bj++)
                #pragma unroll
                for (int mi = 0; mi < 2; mi++) {
                    mma_bf16(acc[mi][bj*2+0], ah[mi], bl[bj][0], bl[bj][1]);
                    mma_bf16(acc[mi][bj*2+1], ah[mi], bl[bj][2], bl[bj][3]);
                }
            #pragma unroll
            for (int bj = 0; bj < 4; bj++)
                #pragma unroll
                for (int mi = 0; mi < 2; mi++) {
                    mma_bf16(acc[mi][bj*2+0], al[mi], bh[bj][0], bh[bj][1]);
                    mma_bf16(acc[mi][bj*2+1], al[mi], bh[bj][2], bh[bj][3]);
                }
        }
        NB_ARRIVE(3 + s);                         // signal EMPTY_s
    }

    // epilogue: D fragments -> g_val
    const int qr = lane >> 2, qc = lane & 3;
    #pragma unroll
    for (int mi = 0; mi < 2; mi++) {
        int row0 = p0 + wm * 32 + mi * 16 + qr;
        float* r0 = g_val + ((size_t)bn * PP + row0) * DDIM;
        float* r1 = r0 + 8 * DDIM;
        #pragma unroll
        for (int nt = 0; nt < 8; nt++) {
            int col = wn * 64 + nt * 8 + qc * 2;
            *(float2*)(r0 + col) = make_float2(acc[mi][nt][0], acc[mi][nt][1]);
            *(float2*)(r1 + col) = make_float2(acc[mi][nt][2], acc[mi][nt][3]);
        }
    }
}

// ---------------------------------------------------------------------------
// K2: homography + bilinear sample + normalized dot + softmax + weighted sum
// ---------------------------------------------------------------------------
__global__ void __launch_bounds__(256) k2_attn()
{
    int b    = blockIdx.y;
    int p    = blockIdx.x * 8 + (threadIdx.x >> 5);
    int lane = threadIdx.x & 31;

    int col = p % WW, row = p / WW;
    float pxc = (float)col * (IMG_W / (float)(WW - 1));
    float pyc = (float)row * (IMG_H / (float)(HH - 1));

    const float4* qptr = (const float4*)(g_val + ((size_t)(b*NN + 0) * PP + p) * DDIM);
    float4 q4 = qptr[lane];
    float qss = wred(q4.x*q4.x + q4.y*q4.y + q4.z*q4.z + q4.w*q4.w);
    float qinv = 1.f / fmaxf(sqrtf(qss), 1e-12f);

    float4 s4[NN];
    float dotv[NN];

    #pragma unroll
    for (int n = 0; n < NN; n++) {
        const float* H = g_Hm + (b*NN + n) * 9;
        float hz = fmaf(H[6], pxc, fmaf(H[7], pyc, H[8]));
        float hx = fmaf(H[0], pxc, fmaf(H[1], pyc, H[2])) / hz;
        float hy = fmaf(H[3], pxc, fmaf(H[4], pyc, H[5])) / hz;
        float sx = hx * ((float)WW / IMG_W);
        float sy = hy * ((float)HH / IMG_H);
        bool valid = (sx >= 0.f) && (sx <= (float)(WW-1)) &&
                     (sy >= 0.f) && (sy <= (float)(HH-1));
        sx = fminf(fmaxf(sx, -1e4f), 1e4f);
        sy = fminf(fmaxf(sy, -1e4f), 1e4f);
        float x0f = floorf(sx), y0f = floorf(sy);
        int   x0 = (int)x0f,    y0 = (int)y0f;
        float fx = sx - x0f, fy = sy - y0f;

        float4 acc = make_float4(0.f, 0.f, 0.f, 0.f);
        const float* vb = g_val + (size_t)(b*NN + n) * PP * DDIM;
        #pragma unroll
        for (int c = 0; c < 4; c++) {
            int cx = x0 + (c & 1);
            int cy = y0 + (c >> 1);
            float wx = (c & 1)  ? fx : 1.f - fx;
            float wy = (c >> 1) ? fy : 1.f - fy;
            if (cx >= 0 && cx < WW && cy >= 0 && cy < HH) {
                const float4* vp = (const float4*)(vb + ((size_t)(cy*WW + cx)) * DDIM) + lane;
                float4 v = *vp;
                float w = wx * wy;
                acc.x = fmaf(w, v.x, acc.x);
                acc.y = fmaf(w, v.y, acc.y);
                acc.z = fmaf(w, v.z, acc.z);
                acc.w = fmaf(w, v.w, acc.w);
            }
        }
        s4[n] = acc;
        float ss = acc.x*acc.x + acc.y*acc.y + acc.z*acc.z + acc.w*acc.w;
        float dd = q4.x*acc.x + q4.y*acc.y + q4.z*acc.z + q4.w*acc.w;
        #pragma unroll
        for (int o = 16; o; o >>= 1) {
            ss += __shfl_xor_sync(0xffffffffu, ss, o);
            dd += __shfl_xor_sync(0xffffffffu, dd, o);
        }
        float sinv = 1.f / fmaxf(sqrtf(ss), 1e-12f);
        dotv[n] = valid ? dd * qinv * sinv : 0.f;
    }

    float m = dotv[0];
    #pragma unroll
    for (int n = 1; n < NN; n++) m = fmaxf(m, dotv[n]);
    float e[NN], se = 0.f;
    #pragma unroll
    for (int n = 0; n < NN; n++) { e[n] = expf(dotv[n] - m); se += e[n]; }
    float inv = 1.f / se;

    float4 o = q4;
    #pragma unroll
    for (int n = 0; n < NN; n++) {
        float a = e[n] * inv;
        o.x = fmaf(a, s4[n].x, o.x);
        o.y = fmaf(a, s4[n].y, o.y);
        o.z = fmaf(a, s4[n].z, o.z);
        o.w = fmaf(a, s4[n].w, o.w);
    }
    float4* zp = (float4*)(g_z + ((size_t)b * PP + p) * DDIM);
    zp[lane] = o;
}

// ---------------------------------------------------------------------------
// K3 (HMMA): LN1 -> GEMM1(64x256x128) -> gelu -> GEMM2(64x128x256)
//            -> residual(LN1 out) -> LN2 -> transposed store
// ---------------------------------------------------------------------------
#define S3_XHI 0
#define S3_XLO 16384
#define S3_WHI 32768
#define S3_WLO 65536
#define S3_HHI 98304
#define S3_HLO 131072
#define K3T_SMEM 163840
#define OS_STRIDE 132

__global__ void __launch_bounds__(256)
k3_mlp_tc(const float* __restrict__ l1g, const float* __restrict__ l1b,
          const float* __restrict__ b1v, const float* __restrict__ b2v,
          const float* __restrict__ l2g, const float* __restrict__ l2b,
          float* __restrict__ out)
{
    extern __shared__ char sm3[];
    const uint32_t sb = smem_u32(sm3);
    const int b  = blockIdx.y;
    const int p0 = blockIdx.x * 64;
    const int t  = threadIdx.x;
    const int lane = t & 31, wid = t >> 5;

    // ---- Phase 0: load z, LN1, write X hi/lo tiles ----
    {
        const float* zb = g_z + ((size_t)b * PP + p0) * DDIM;
        float4 g  = *(const float4*)(l1g + lane * 4);
        float4 be = *(const float4*)(l1b + lane * 4);
        #pragma unroll
        for (int rr = 0; rr < 8; rr++) {
            int row = wid * 8 + rr;
            float4 v = *(const float4*)(zb + (size_t)row * DDIM + lane * 4);
            float s  = wred(v.x + v.y + v.z + v.w);
            float s2 = wred(v.x*v.x + v.y*v.y + v.z*v.z + v.w*v.w);
            float mu = s * (1.f/128.f);
            float var = s2 * (1.f/128.f) - mu*mu;
            float rs = rsqrtf(var + 1e-5f);
            float x0 = (v.x - mu) * rs * g.x + be.x;
            float x1 = (v.y - mu) * rs * g.y + be.y;
            float x2 = (v.z - mu) * rs * g.z + be.z;
            float x3 = (v.w - mu) * rs * g.w + be.w;
            uint2 pA = split_pack(x0, x1);
            uint2 pB = split_pack(x2, x3);
            uint32_t base = (uint32_t)(lane >> 4) * 8192 + (uint32_t)row * 128;
            uint32_t o0 = base + ((((lane & 15) * 8) + 0) ^ ((row & 7) << 4));
            uint32_t o1 = base + ((((lane & 15) * 8) + 4) ^ ((row & 7) << 4));
            *(uint32_t*)(sm3 + S3_XHI + o0) = pA.x;
            *(uint32_t*)(sm3 + S3_XLO + o0) = pA.y;
            *(uint32_t*)(sm3 + S3_XHI + o1) = pB.x;
            *(uint32_t*)(sm3 + S3_XLO + o1) = pB.y;
        }
    }
    __syncthreads();

    const int wm = wid & 1;
    const int wn = wid >> 1;
    const int qr = lane >> 2, qc = lane & 3;

    // ---- GEMM1: H[64x256] = X[64x128] @ W1 ----
    float acc[2][8][4];
    #pragma unroll
    for (int mi = 0; mi < 2; mi++)
        #pragma unroll
        for (int nt = 0; nt < 8; nt++)
            #pragma unroll
            for (int j = 0; j < 4; j++) acc[mi][nt][j] = 0.f;

    for (int kc = 0; kc < 2; kc++) {
        #pragma unroll 4
        for (int i = 0; i < 32; i++) {
            int idx = t + i * 256;
            int kpl = idx & 31, nl = idx >> 5;
            uint2 w = g_w1p[nl * 64 + kc * 32 + kpl];
            uint32_t off = (uint32_t)nl * 128 + (((uint32_t)kpl * 4) ^ ((nl & 7) << 4));
            *(uint32_t*)(sm3 + S3_WHI + off) = w.x;
            *(uint32_t*)(sm3 + S3_WLO + off) = w.y;
        }
        __syncthreads();

        #pragma unroll
        for (int ks = 0; ks < 4; ks++) {
            const uint32_t kb = (uint32_t)ks * 32;
            uint32_t ah[2][4], al[2][4];
            #pragma unroll
            for (int mi = 0; mi < 2; mi++) {
                uint32_t row = (uint32_t)(wm * 32 + mi * 16 + (lane & 15));
                uint32_t kby = kb + ((lane >> 4) << 4);
                uint32_t off = (uint32_t)kc * 8192 + row * 128 + (kby ^ ((row & 7) << 4));
                ldsm_x4(ah[mi], sb + S3_XHI + off);
                ldsm_x4(al[mi], sb + S3_XLO + off);
            }
            #pragma unroll
            for (int bj = 0; bj < 4; bj++) {
                uint32_t rown = (uint32_t)(wn * 64 + bj * 16 + (lane & 7) + ((lane >> 4) << 3));
                uint32_t kby  = kb + (((lane >> 3) & 1) << 4);
                uint32_t off  = rown * 128 + (kby ^ ((rown & 7) << 4));
                uint32_t bh[4], bl[4];
                ldsm_x4(bh, sb + S3_WHI + off);
                ldsm_x4(bl, sb + S3_WLO + off);
                #pragma unroll
                for (int mi = 0; mi < 2; mi++) {
                    mma_bf16(acc[mi][bj*2+0], ah[mi], bh[0], bh[1]);
                    mma_bf16(acc[mi][bj*2+0], ah[mi], bl[0], bl[1]);
                    mma_bf16(acc[mi][bj*2+0], al[mi], bh[0], bh[1]);
                    mma_bf16(acc[mi][bj*2+1], ah[mi], bh[2], bh[3]);
                    mma_bf16(acc[mi][bj*2+1], ah[mi], bl[2], bl[3]);
                    mma_bf16(acc[mi][bj*2+1], al[mi], bh[2], bh[3]);
                }
            }
        }
        __syncthreads();
    }

    // ---- gelu + write H tiles (chunk = wn) ----
    {
        #pragma unroll
        for (int mi = 0; mi < 2; mi++) {
            int R0 = wm * 32 + mi * 16 + qr;
            int R1 = R0 + 8;
            #pragma unroll
            for (int nt = 0; nt < 8; nt++) {
                int C = wn * 64 + nt * 8 + qc * 2;
                float h00 = geluf(acc[mi][nt][0] + b1v[C]);
                float h01 = geluf(acc[mi][nt][1] + b1v[C+1]);
                float h10 = geluf(acc[mi][nt][2] + b1v[C]);
                float h11 = geluf(acc[mi][nt][3] + b1v[C+1]);
                uint2 pA = split_pack(h00, h01);
                uint2 pB = split_pack(h10, h11);
                uint32_t base = (uint32_t)wn * 8192;
                uint32_t kloc = (uint32_t)(nt * 16 + qc * 4);
                uint32_t oA = base + (uint32_t)R0 * 128 + (kloc ^ ((R0 & 7) << 4));
                uint32_t oB = base + (uint32_t)R1 * 128 + (kloc ^ ((R1 & 7) << 4));
                *(uint32_t*)(sm3 + S3_HHI + oA) = pA.x;
                *(uint32_t*)(sm3 + S3_HLO + oA) = pA.y;
                *(uint32_t*)(sm3 + S3_HHI + oB) = pB.x;
                *(uint32_t*)(sm3 + S3_HLO + oB) = pB.y;
            }
        }
    }
    __syncthreads();

    // ---- GEMM2: O[64x128] = H[64x256] @ W2 ----
    float acc2[2][4][4];
    #pragma unroll
    for (int mi = 0; mi < 2; mi++)
        #pragma unroll
        for (int nt = 0; nt < 4; nt++)
            #pragma unroll
            for (int j = 0; j < 4; j++) acc2[mi][nt][j] = 0.f;

    for (int kc = 0; kc < 4; kc++) {
        #pragma unroll 4
        for (int i = 0; i < 16; i++) {
            int idx = t + i * 256;
            int kpl = idx & 31, nl = idx >> 5;
            uint2 w = g_w2p[nl * 128 + kc * 32 + kpl];
            uint32_t off = (uint32_t)nl * 128 + (((uint32_t)kpl * 4) ^ ((nl & 7) << 4));
            *(uint32_t*)(sm3 + S3_WHI + off) = w.x;
            *(uint32_t*)(sm3 + S3_WLO + off) = w.y;
        }
        __syncthreads();

        #pragma unroll
        for (int ks = 0; ks < 4; ks++) {
            const uint32_t kb = (uint32_t)ks * 32;
            uint32_t ah[2][4], al[2][4];
            #pragma unroll
            for (int mi = 0; mi < 2; mi++) {
                uint32_t row = (uint32_t)(wm * 32 + mi * 16 + (lane & 15));
                uint32_t kby = kb + ((lane >> 4) << 4);
                uint32_t off = (uint32_t)kc * 8192 + row * 128 + (kby ^ ((row & 7) << 4));
                ldsm_x4(ah[mi], sb + S3_HHI + off);
                ldsm_x4(al[mi], sb + S3_HLO + off);
            }
            #pragma unroll
            for (int bj = 0; bj < 2; bj++) {
                uint32_t rown = (uint32_t)(wn * 32 + bj * 16 + (lane & 7) + ((lane >> 4) << 3));
                uint32_t kby  = kb + (((lane >> 3) & 1) << 4);
                uint32_t off  = rown * 128 + (kby ^ ((rown & 7) << 4));
                uint32_t bh[4], bl[4];
                ldsm_x4(bh, sb + S3_WHI + off);
                ldsm_x4(bl, sb + S3_WLO + off);
                #pragma unroll
                for (int mi = 0; mi < 2; mi++) {
                    mma_bf16(acc2[mi][bj*2+0], ah[mi], bh[0], bh[1]);
                    mma_bf16(acc2[mi][bj*2+0], ah[mi], bl[0], bl[1]);
                    mma_bf16(acc2[mi][bj*2+0], al[mi], bh[0], bh[1]);
                    mma_bf16(acc2[mi][bj*2+1], ah[mi], bh[2], bh[3]);
                    mma_bf16(acc2[mi][bj*2+1], ah[mi], bl[2], bl[3]);
                    mma_bf16(acc2[mi][bj*2+1], al[mi], bh[2], bh[3]);
                }
            }
        }
        __syncthreads();
    }

    // ---- epilogue: residual + bias ----
    float* outstage = (float*)(sm3 + S3_WHI);
    {
        #pragma unroll
        for (int mi = 0; mi < 2; mi++) {
            #pragma unroll
            for (int nt = 0; nt < 4; nt++) {
                int C = wn * 32 + nt * 8 + qc * 2;
                float bC0 = b2v[C], bC1 = b2v[C+1];
                #pragma unroll
                for (int rh = 0; rh < 2; rh++) {
                    int R = wm * 32 + mi * 16 + qr + rh * 8;
                    uint32_t off = (uint32_t)(C >> 6) * 8192 + (uint32_t)R * 128 +
                                   ((((uint32_t)(C & 63)) * 2) ^ ((R & 7) << 4));
                    uint32_t xh = *(uint32_t*)(sm3 + S3_XHI + off);
                    uint32_t xl = *(uint32_t*)(sm3 + S3_XLO + off);
                    float r0 = bflo_f(xh) + bflo_f(xl);
                    float r1 = bfhi_f(xh) + bfhi_f(xl);
                    outstage[R * OS_STRIDE + C]     = r0 + acc2[mi][nt][rh*2+0] + bC0;
                    outstage[R * OS_STRIDE + C + 1] = r1 + acc2[mi][nt][rh*2+1] + bC1;
                }
            }
        }
    }
    __syncthreads();

    // ---- LN2 ----
    #pragma unroll
    for (int k = 0; k < 8; k++) {
        int pp = wid * 8 + k;
        float v0 = outstage[pp*OS_STRIDE + lane];
        float v1 = outstage[pp*OS_STRIDE + lane + 32];
        float v2 = outstage[pp*OS_STRIDE + lane + 64];
        float v3 = outstage[pp*OS_STRIDE + lane + 96];
        float s  = wred(v0+v1+v2+v3);
        float s2 = wred(v0*v0+v1*v1+v2*v2+v3*v3);
        float mu = s * (1.f/128.f);
        float var = s2 * (1.f/128.f) - mu*mu;
        float rs = rsqrtf(var + 1e-5f);
        outstage[pp*OS_STRIDE + lane]      = (v0-mu)*rs*l2g[lane]    + l2b[lane];
        outstage[pp*OS_STRIDE + lane + 32] = (v1-mu)*rs*l2g[lane+32] + l2b[lane+32];
        outstage[pp*OS_STRIDE + lane + 64] = (v2-mu)*rs*l2g[lane+64] + l2b[lane+64];
        outstage[pp*OS_STRIDE + lane + 96] = (v3-mu)*rs*l2g[lane+96] + l2b[lane+96];
    }
    __syncthreads();

    // ---- transposed store ----
    for (int i = t; i < 64 * DDIM; i += 256) {
        int d = i >> 6, pp = i & 63;
        out[((size_t)b * DDIM + d) * PP + p0 + pp] = outstage[pp * OS_STRIDE + d];
    }
}

// ---------------------------------------------------------------------------
extern "C" void kernel_launch(void* const* d_in, const int* in_sizes, int n_in,
                              void* d_out, int out_size)
{
    const float* feature   = (const float*)d_in[0];
    const float* I_src     = (const float*)d_in[1];
    const float* I_tar_inv = (const float*)d_in[2];
    const float* E         = (const float*)d_in[3];
    const float* dis       = (const float*)d_in[4];
    const float* norm_vec  = (const float*)d_in[5];
    const float* bn_gamma  = (const float*)d_in[6];
    const float* bn_beta   = (const float*)d_in[7];
    const float* bn_mean   = (const float*)d_in[8];
    const float* bn_var    = (const float*)d_in[9];
    const float* conv_w    = (const float*)d_in[10];
    const float* ln1_g     = (const float*)d_in[11];
    const float* ln1_b     = (const float*)d_in[12];
    const float* mlp_w1    = (const float*)d_in[13];
    const float* mlp_b1    = (const float*)d_in[14];
    const float* mlp_w2    = (const float*)d_in[15];
    const float* mlp_b2    = (const float*)d_in[16];
    const float* ln2_g     = (const float*)d_in[17];
    const float* ln2_b     = (const float*)d_in[18];
    float* out = (float*)d_out;

    cudaFuncSetAttribute(k1_conv_tc,
                         cudaFuncAttributeMaxDynamicSharedMemorySize, K1_SMEM);
    cudaFuncSetAttribute(k3_mlp_tc,
                         cudaFuncAttributeMaxDynamicSharedMemorySize, K3T_SMEM);

    k0_prep<<<1, 256>>>(I_src, I_tar_inv, E, dis, norm_vec,
                        bn_gamma, bn_beta, bn_mean, bn_var);
    k0b_pack<<<64, 256>>>(conv_w, mlp_w1, mlp_w2);
    k1_conv_tc<<<dim3(PP/128, BN), 384, K1_SMEM>>>(feature);
    k2_attn<<<dim3(PP/8, BB), 256>>>();
    k3_mlp_tc<<<dim3(PP/64, BB), 256, K3T_SMEM>>>(ln1_g, ln1_b, mlp_b1, mlp_b2,
                                                  ln2_g, ln2_b, out);
}

// round 15
// speedup vs baseline: 1.0895x; 1.0895x over previous
#include <cuda_runtime.h>
#include <cuda_bf16.h>
#include <math.h>
#include <stdint.h>

// Problem constants
#define BB 4
#define NN 6
#define FDIM 256
#define DDIM 128
#define HH 64
#define WW 120
#define PP (HH*WW)          // 7680
#define BN (BB*NN)          // 24
#define IMG_H 480.0f
#define IMG_W 960.0f

// Scratch (device globals — no runtime allocation allowed)
__device__ float g_val[(size_t)BN * PP * DDIM];   // (bn, p, d)  94.4 MB
__device__ float g_z[(size_t)BB * PP * DDIM];     // (b, p, d)   15.7 MB
__device__ float g_Hm[BN * 9];
__device__ float g_bnscale[FDIM];
__device__ float g_bnshift[FDIM];
// Prepacked split-bf16 weights
__device__ uint32_t g_wch[128 * 128];  // conv_w hi pairs [d][kpair]
__device__ uint32_t g_wcl[128 * 128];  // conv_w lo pairs
__device__ uint2 g_w1p[256 * 64];      // W1^T  [n=256][kpair=64]
__device__ uint2 g_w2p[128 * 128];     // W2^T  [n=128][kpair=128]

// ===========================================================================
// helpers: sm_80-baseline tensor path (ldmatrix + mma.sync) — no 'a' features
// ===========================================================================
__device__ __forceinline__ uint32_t smem_u32(const void* p) {
    uint32_t a;
    asm("{ .reg .u64 t; cvta.to.shared.u64 t, %1; cvt.u32.u64 %0, t; }"
        : "=r"(a) : "l"(p));
    return a;
}
__device__ __forceinline__ void ldsm_x4(uint32_t* r, uint32_t addr) {
    asm volatile("ldmatrix.sync.aligned.m8n8.x4.shared.b16 {%0,%1,%2,%3}, [%4];"
        : "=r"(r[0]), "=r"(r[1]), "=r"(r[2]), "=r"(r[3]) : "r"(addr));
}
__device__ __forceinline__ void mma_bf16(float* c, const uint32_t* a,
                                         uint32_t b0, uint32_t b1) {
    asm volatile(
        "mma.sync.aligned.m16n8k16.row.col.f32.bf16.bf16.f32 "
        "{%0,%1,%2,%3}, {%4,%5,%6,%7}, {%8,%9}, {%0,%1,%2,%3};"
        : "+f"(c[0]), "+f"(c[1]), "+f"(c[2]), "+f"(c[3])
        : "r"(a[0]), "r"(a[1]), "r"(a[2]), "r"(a[3]), "r"(b0), "r"(b1));
}
__device__ __forceinline__ void cp_async16(uint32_t smem_addr, const void* gptr) {
    asm volatile("cp.async.ca.shared.global [%0], [%1], 16;"
        :: "r"(smem_addr), "l"(gptr) : "memory");
}
__device__ __forceinline__ uint32_t pack_bf16x2(__nv_bfloat16 lo, __nv_bfloat16 hi) {
    return ((uint32_t)__bfloat16_as_ushort(hi) << 16) | __bfloat16_as_ushort(lo);
}
__device__ __forceinline__ uint2 split_pack(float a, float b) {
    __nv_bfloat16 ha = __float2bfloat16(a), hb = __float2bfloat16(b);
    __nv_bfloat16 la = __float2bfloat16(a - __bfloat162float(ha));
    __nv_bfloat16 lb = __float2bfloat16(b - __bfloat162float(hb));
    return make_uint2(pack_bf16x2(ha, hb), pack_bf16x2(la, lb));
}
__device__ __forceinline__ float bflo_f(uint32_t u) { return __uint_as_float(u << 16); }
__device__ __forceinline__ float bfhi_f(uint32_t u) { return __uint_as_float(u & 0xffff0000u); }
__device__ __forceinline__ float geluf(float h) {
    return 0.5f * h * (1.f + erff(h * 0.70710678118654752f));
}
__device__ __forceinline__ float wred(float v) {
    #pragma unroll
    for (int o = 16; o; o >>= 1) v += __shfl_xor_sync(0xffffffffu, v, o);
    return v;
}

// ---------------------------------------------------------------------------
// K0: homographies + BN scale/shift
// ---------------------------------------------------------------------------
__global__ void k0_prep(const float* __restrict__ I_src,
                        const float* __restrict__ I_tar_inv,
                        const float* __restrict__ E,
                        const float* __restrict__ disp,
                        const float* __restrict__ nvec,
                        const float* __restrict__ bng,
                        const float* __restrict__ bnb,
                        const float* __restrict__ bnm,
                        const float* __restrict__ bnv)
{
    int t = threadIdx.x;
    if (t < FDIM) {
        float sc = bng[t] * rsqrtf(bnv[t] + 1e-5f);
        g_bnscale[t] = sc;
        g_bnshift[t] = bnb[t] - bnm[t] * sc;
    }
    if (t < BN) {
        int b = t / NN;
        float dis = disp[0];
        const float* Eb = E + t * 16;
        const float* Ks = I_src + t * 9;
        const float* Kt = I_tar_inv + b * 9;
        float nv0 = nvec[b*3+0], nv1 = nvec[b*3+1], nv2 = nvec[b*3+2];
        float A[9];
        #pragma unroll
        for (int i = 0; i < 3; i++) {
            float Ti = Eb[i*4+3] / dis;
            A[i*3+0] = Eb[i*4+0] - Ti * nv0;
            A[i*3+1] = Eb[i*4+1] - Ti * nv1;
            A[i*3+2] = Eb[i*4+2] - Ti * nv2;
        }
        float M[9];
        #pragma unroll
        for (int i = 0; i < 3; i++)
            #pragma unroll
            for (int j = 0; j < 3; j++)
                M[i*3+j] = Ks[i*3+0]*A[0*3+j] + Ks[i*3+1]*A[1*3+j] + Ks[i*3+2]*A[2*3+j];
        #pragma unroll
        for (int i = 0; i < 3; i++)
            #pragma unroll
            for (int j = 0; j < 3; j++)
                g_Hm[t*9 + i*3+j] = M[i*3+0]*Kt[0*3+j] + M[i*3+1]*Kt[1*3+j] + M[i*3+2]*Kt[2*3+j];
    }
}

// ---------------------------------------------------------------------------
// K0b1: pack conv_w split-bf16 hi/lo pair arrays
// ---------------------------------------------------------------------------
__global__ void k0b1_pack(const float* __restrict__ Wc)
{
    int i = blockIdx.x * 256 + threadIdx.x;   // 0..16383
    int d = i >> 7, fp = i & 127;
    uint2 p = split_pack(Wc[d*256 + fp*2], Wc[d*256 + fp*2 + 1]);
    g_wch[i] = p.x;
    g_wcl[i] = p.y;
}

// ---------------------------------------------------------------------------
// K0b2: pack W1^T / W2^T split-bf16 pair arrays
// ---------------------------------------------------------------------------
__global__ void k0b2_pack(const float* __restrict__ W1,
                          const float* __restrict__ W2)
{
    int i = blockIdx.x * 256 + threadIdx.x;   // 0..16383
    {   // W2^T: g_w2p[n=d][kpair over j], W2 is [256 j][128 d]
        int d = i >> 7, kp = i & 127;
        g_w2p[i] = split_pack(W2[(kp*2)*128 + d], W2[(kp*2+1)*128 + d]);
    }
    {   // W1^T: g_w1p[n=j][kpair over d], W1 is [128 d][256 j]
        int j = i >> 6, kp = i & 63;
        g_w1p[i] = split_pack(W1[(kp*2)*256 + j], W1[(kp*2+1)*256 + j]);
    }
}

// ---------------------------------------------------------------------------
// K1 (HMMA, 2-stage pipelined, term-major, interleaved convert):
// val[bn][p][d] = sum_f W[d][f]*relu(bn(feat))
// CTA tile 128px(M) x 128d(N), K-chunks of 64, double-buffered smem (128 KB).
// The X(c+1) convert+STS is interleaved into the MMA k-step loop (4 pairs
// per k-step) to fill idle issue slots during HMMA execution.
// ---------------------------------------------------------------------------
#define K1_SMEM 131072

__global__ void __launch_bounds__(256)
k1_conv_tc(const float* __restrict__ feat)
{
    extern __shared__ char smem[];
    const uint32_t sb = smem_u32(smem);
    const int bn = blockIdx.y;
    const int p0 = blockIdx.x * 128;
    const int t  = threadIdx.x;
    const int wid = t >> 5, lane = t & 31;
    const int wm = wid & 3;    // M quarter
    const int wn = wid >> 2;   // N half
    const int pl  = t & 127;   // X producer: pixel row
    const int fp0 = t >> 7;    // kpair phase 0/1

    float acc[2][8][4];
    #pragma unroll
    for (int mi = 0; mi < 2; mi++)
        #pragma unroll
        for (int nt = 0; nt < 8; nt++)
            #pragma unroll
            for (int j = 0; j < 4; j++) acc[mi][nt][j] = 0.f;

    const float* fb = feat + (size_t)bn * FDIM * PP + p0;

    // ---- prologue: stage 0 = chunk 0 ----
    #pragma unroll
    for (int i = 0; i < 4; i++) {           // W chunk 0 via cp.async
        int idx = t + i * 256;              // 16B-unit 0..1023
        int kq = idx & 7, dl = idx >> 3;
        uint32_t off = (uint32_t)dl * 128 + (((uint32_t)kq * 16) ^ ((dl & 7) << 4));
        cp_async16(sb + 65536 + off,          g_wch + dl * 128 + kq * 4);
        cp_async16(sb + 65536 + 16384 + off,  g_wcl + dl * 128 + kq * 4);
    }
    asm volatile("cp.async.commit_group;" ::: "memory");
    #pragma unroll
    for (int i = 0; i < 16; i++) {          // X chunk 0 direct
        int fp = fp0 + 2 * i;               // kpair 0..31
        int f  = 2 * fp;
        float v0 = fb[(size_t)f       * PP + pl];
        float v1 = fb[(size_t)(f + 1) * PP + pl];
        v0 = fmaxf(fmaf(v0, g_bnscale[f],   g_bnshift[f]),   0.f);
        v1 = fmaxf(fmaf(v1, g_bnscale[f+1], g_bnshift[f+1]), 0.f);
        uint2 p = split_pack(v0, v1);
        uint32_t off = (uint32_t)pl * 128 + (((uint32_t)fp * 4) ^ ((pl & 7) << 4));
        *(uint32_t*)(smem + off)         = p.x;
        *(uint32_t*)(smem + 16384 + off) = p.y;
    }

    for (int c = 0; c < 4; c++) {
        const int s = c & 1;
        const uint32_t xbase = sb + (uint32_t)s * 32768;
        const uint32_t wbase = sb + 65536 + (uint32_t)s * 32768;

        // prefetch next chunk's X into registers (latency hidden by MMAs)
        float v0r[16], v1r[16];
        if (c < 3) {
            const int f0n = (c + 1) * 64;
            #pragma unroll
            for (int i = 0; i < 16; i++) {
                int f = f0n + 2 * (fp0 + 2 * i);
                v0r[i] = fb[(size_t)f       * PP + pl];
                v1r[i] = fb[(size_t)(f + 1) * PP + pl];
            }
        }

        asm volatile("cp.async.wait_group 0;" ::: "memory");
        __syncthreads();   // stage s fully ready; stage s^1 free

        // issue W cp.async for chunk c+1 into stage s^1 (overlaps MMAs)
        if (c < 3) {
            #pragma unroll
            for (int i = 0; i < 4; i++) {
                int idx = t + i * 256;
                int kq = idx & 7, dl = idx >> 3;
                uint32_t off = (uint32_t)dl * 128 + (((uint32_t)kq * 16) ^ ((dl & 7) << 4));
                const uint32_t wb1 = sb + 65536 + (uint32_t)(s ^ 1) * 32768;
                cp_async16(wb1 + off,         g_wch + dl * 128 + (c + 1) * 32 + kq * 4);
                cp_async16(wb1 + 16384 + off, g_wcl + dl * 128 + (c + 1) * 32 + kq * 4);
            }
            asm volatile("cp.async.commit_group;" ::: "memory");
        }

        char* xdst = smem + (size_t)(s ^ 1) * 32768;
        const int f0n = (c + 1) * 64;

        // ---- MMAs on stage s, with X(c+1) convert interleaved per k-step ----
        #pragma unroll
        for (int ks = 0; ks < 4; ks++) {
            const uint32_t kb = (uint32_t)ks * 32;
            uint32_t ah[2][4], al[2][4];
            #pragma unroll
            for (int mi = 0; mi < 2; mi++) {
                uint32_t row = (uint32_t)(wm * 32 + mi * 16 + (lane & 15));
                uint32_t kby = kb + ((lane >> 4) << 4);
                uint32_t off = row * 128 + (kby ^ ((row & 7) << 4));
                ldsm_x4(ah[mi], xbase + off);
                ldsm_x4(al[mi], xbase + 16384 + off);
            }
            uint32_t bh[4][4], bl[4][4];
            #pragma unroll
            for (int bj = 0; bj < 4; bj++) {
                uint32_t rown = (uint32_t)(wn * 64 + bj * 16 + (lane & 7) + ((lane >> 4) << 3));
                uint32_t kby  = kb + (((lane >> 3) & 1) << 4);
                uint32_t off  = rown * 128 + (kby ^ ((rown & 7) << 4));
                ldsm_x4(bh[bj], wbase + off);
                ldsm_x4(bl[bj], wbase + 16384 + off);
            }
            // term-major: hh -> hl -> lh
            #pragma unroll
            for (int bj = 0; bj < 4; bj++)
                #pragma unroll
                for (int mi = 0; mi < 2; mi++) {
                    mma_bf16(acc[mi][bj*2+0], ah[mi], bh[bj][0], bh[bj][1]);
                    mma_bf16(acc[mi][bj*2+1], ah[mi], bh[bj][2], bh[bj][3]);
                }
            #pragma unroll
            for (int bj = 0; bj < 4; bj++)
                #pragma unroll
                for (int mi = 0; mi < 2; mi++) {
                    mma_bf16(acc[mi][bj*2+0], ah[mi], bl[bj][0], bl[bj][1]);
                    mma_bf16(acc[mi][bj*2+1], ah[mi], bl[bj][2], bl[bj][3]);
                }
            #pragma unroll
            for (int bj = 0; bj < 4; bj++)
                #pragma unroll
                for (int mi = 0; mi < 2; mi++) {
                    mma_bf16(acc[mi][bj*2+0], al[mi], bh[bj][0], bh[bj][1]);
                    mma_bf16(acc[mi][bj*2+1], al[mi], bh[bj][2], bh[bj][3]);
                }
            // interleaved convert: 4 pairs of X(c+1) per k-step
            if (c < 3) {
                #pragma unroll
                for (int g = 0; g < 4; g++) {
                    int i  = ks * 4 + g;
                    int fp = fp0 + 2 * i;
                    int f  = f0n + 2 * fp;
                    float v0 = fmaxf(fmaf(v0r[i], g_bnscale[f],   g_bnshift[f]),   0.f);
                    float v1 = fmaxf(fmaf(v1r[i], g_bnscale[f+1], g_bnshift[f+1]), 0.f);
                    uint2 p = split_pack(v0, v1);
                    uint32_t off = (uint32_t)pl * 128 + (((uint32_t)fp * 4) ^ ((pl & 7) << 4));
                    *(uint32_t*)(xdst + off)         = p.x;
                    *(uint32_t*)(xdst + 16384 + off) = p.y;
                }
            }
        }
    }

    const int qr = lane >> 2, qc = lane & 3;
    #pragma unroll
    for (int mi = 0; mi < 2; mi++) {
        int row0 = p0 + wm * 32 + mi * 16 + qr;
        float* r0 = g_val + ((size_t)bn * PP + row0) * DDIM;
        float* r1 = r0 + 8 * DDIM;
        #pragma unroll
        for (int nt = 0; nt < 8; nt++) {
            int col = wn * 64 + nt * 8 + qc * 2;
            *(float2*)(r0 + col) = make_float2(acc[mi][nt][0], acc[mi][nt][1]);
            *(float2*)(r1 + col) = make_float2(acc[mi][nt][2], acc[mi][nt][3]);
        }
    }
}

// ---------------------------------------------------------------------------
// K2: homography + bilinear sample + normalized dot + softmax + weighted sum
// ---------------------------------------------------------------------------
__global__ void __launch_bounds__(256) k2_attn()
{
    int b    = blockIdx.y;
    int p    = blockIdx.x * 8 + (threadIdx.x >> 5);
    int lane = threadIdx.x & 31;

    int col = p % WW, row = p / WW;
    float pxc = (float)col * (IMG_W / (float)(WW - 1));
    float pyc = (float)row * (IMG_H / (float)(HH - 1));

    const float4* qptr = (const float4*)(g_val + ((size_t)(b*NN + 0) * PP + p) * DDIM);
    float4 q4 = qptr[lane];
    float qss = wred(q4.x*q4.x + q4.y*q4.y + q4.z*q4.z + q4.w*q4.w);
    float qinv = 1.f / fmaxf(sqrtf(qss), 1e-12f);

    float4 s4[NN];
    float dotv[NN];

    #pragma unroll
    for (int n = 0; n < NN; n++) {
        const float* H = g_Hm + (b*NN + n) * 9;
        float hz = fmaf(H[6], pxc, fmaf(H[7], pyc, H[8]));
        float hx = fmaf(H[0], pxc, fmaf(H[1], pyc, H[2])) / hz;
        float hy = fmaf(H[3], pxc, fmaf(H[4], pyc, H[5])) / hz;
        float sx = hx * ((float)WW / IMG_W);
        float sy = hy * ((float)HH / IMG_H);
        bool valid = (sx >= 0.f) && (sx <= (float)(WW-1)) &&
                     (sy >= 0.f) && (sy <= (float)(HH-1));
        sx = fminf(fmaxf(sx, -1e4f), 1e4f);
        sy = fminf(fmaxf(sy, -1e4f), 1e4f);
        float x0f = floorf(sx), y0f = floorf(sy);
        int   x0 = (int)x0f,    y0 = (int)y0f;
        float fx = sx - x0f, fy = sy - y0f;

        float4 acc = make_float4(0.f, 0.f, 0.f, 0.f);
        const float* vb = g_val + (size_t)(b*NN + n) * PP * DDIM;
        #pragma unroll
        for (int c = 0; c < 4; c++) {
            int cx = x0 + (c & 1);
            int cy = y0 + (c >> 1);
            float wx = (c & 1)  ? fx : 1.f - fx;
            float wy = (c >> 1) ? fy : 1.f - fy;
            if (cx >= 0 && cx < WW && cy >= 0 && cy < HH) {
                const float4* vp = (const float4*)(vb + ((size_t)(cy*WW + cx)) * DDIM) + lane;
                float4 v = *vp;
                float w = wx * wy;
                acc.x = fmaf(w, v.x, acc.x);
                acc.y = fmaf(w, v.y, acc.y);
                acc.z = fmaf(w, v.z, acc.z);
                acc.w = fmaf(w, v.w, acc.w);
            }
        }
        s4[n] = acc;
        float ss = acc.x*acc.x + acc.y*acc.y + acc.z*acc.z + acc.w*acc.w;
        float dd = q4.x*acc.x + q4.y*acc.y + q4.z*acc.z + q4.w*acc.w;
        #pragma unroll
        for (int o = 16; o; o >>= 1) {
            ss += __shfl_xor_sync(0xffffffffu, ss, o);
            dd += __shfl_xor_sync(0xffffffffu, dd, o);
        }
        float sinv = 1.f / fmaxf(sqrtf(ss), 1e-12f);
        dotv[n] = valid ? dd * qinv * sinv : 0.f;
    }

    float m = dotv[0];
    #pragma unroll
    for (int n = 1; n < NN; n++) m = fmaxf(m, dotv[n]);
    float e[NN], se = 0.f;
    #pragma unroll
    for (int n = 0; n < NN; n++) { e[n] = expf(dotv[n] - m); se += e[n]; }
    float inv = 1.f / se;

    float4 o = q4;
    #pragma unroll
    for (int n = 0; n < NN; n++) {
        float a = e[n] * inv;
        o.x = fmaf(a, s4[n].x, o.x);
        o.y = fmaf(a, s4[n].y, o.y);
        o.z = fmaf(a, s4[n].z, o.z);
        o.w = fmaf(a, s4[n].w, o.w);
    }
    float4* zp = (float4*)(g_z + ((size_t)b * PP + p) * DDIM);
    zp[lane] = o;
}

// ---------------------------------------------------------------------------
// K3 (HMMA): LN1 -> GEMM1(64x256x128) -> gelu -> GEMM2(64x128x256)
//            -> residual(LN1 out) -> LN2 -> transposed store
// ---------------------------------------------------------------------------
#define S3_XHI 0
#define S3_XLO 16384
#define S3_WHI 32768
#define S3_WLO 65536
#define S3_HHI 98304
#define S3_HLO 131072
#define K3T_SMEM 163840
#define OS_STRIDE 132

__global__ void __launch_bounds__(256)
k3_mlp_tc(const float* __restrict__ l1g, const float* __restrict__ l1b,
          const float* __restrict__ b1v, const float* __restrict__ b2v,
          const float* __restrict__ l2g, const float* __restrict__ l2b,
          float* __restrict__ out)
{
    extern __shared__ char sm3[];
    const uint32_t sb = smem_u32(sm3);
    const int b  = blockIdx.y;
    const int p0 = blockIdx.x * 64;
    const int t  = threadIdx.x;
    const int lane = t & 31, wid = t >> 5;

    // ---- Phase 0: load z, LN1, write X hi/lo tiles ----
    {
        const float* zb = g_z + ((size_t)b * PP + p0) * DDIM;
        float4 g  = *(const float4*)(l1g + lane * 4);
        float4 be = *(const float4*)(l1b + lane * 4);
        #pragma unroll
        for (int rr = 0; rr < 8; rr++) {
            int row = wid * 8 + rr;
            float4 v = *(const float4*)(zb + (size_t)row * DDIM + lane * 4);
            float s  = wred(v.x + v.y + v.z + v.w);
            float s2 = wred(v.x*v.x + v.y*v.y + v.z*v.z + v.w*v.w);
            float mu = s * (1.f/128.f);
            float var = s2 * (1.f/128.f) - mu*mu;
            float rs = rsqrtf(var + 1e-5f);
            float x0 = (v.x - mu) * rs * g.x + be.x;
            float x1 = (v.y - mu) * rs * g.y + be.y;
            float x2 = (v.z - mu) * rs * g.z + be.z;
            float x3 = (v.w - mu) * rs * g.w + be.w;
            uint2 pA = split_pack(x0, x1);
            uint2 pB = split_pack(x2, x3);
            uint32_t base = (uint32_t)(lane >> 4) * 8192 + (uint32_t)row * 128;
            uint32_t o0 = base + ((((lane & 15) * 8) + 0) ^ ((row & 7) << 4));
            uint32_t o1 = base + ((((lane & 15) * 8) + 4) ^ ((row & 7) << 4));
            *(uint32_t*)(sm3 + S3_XHI + o0) = pA.x;
            *(uint32_t*)(sm3 + S3_XLO + o0) = pA.y;
            *(uint32_t*)(sm3 + S3_XHI + o1) = pB.x;
            *(uint32_t*)(sm3 + S3_XLO + o1) = pB.y;
        }
    }
    __syncthreads();

    const int wm = wid & 1;
    const int wn = wid >> 1;
    const int qr = lane >> 2, qc = lane & 3;

    // ---- GEMM1: H[64x256] = X[64x128] @ W1 ----
    float acc[2][8][4];
    #pragma unroll
    for (int mi = 0; mi < 2; mi++)
        #pragma unroll
        for (int nt = 0; nt < 8; nt++)
            #pragma unroll
            for (int j = 0; j < 4; j++) acc[mi][nt][j] = 0.f;

    for (int kc = 0; kc < 2; kc++) {
        #pragma unroll 4
        for (int i = 0; i < 32; i++) {
            int idx = t + i * 256;
            int kpl = idx & 31, nl = idx >> 5;
            uint2 w = g_w1p[nl * 64 + kc * 32 + kpl];
            uint32_t off = (uint32_t)nl * 128 + (((uint32_t)kpl * 4) ^ ((nl & 7) << 4));
            *(uint32_t*)(sm3 + S3_WHI + off) = w.x;
            *(uint32_t*)(sm3 + S3_WLO + off) = w.y;
        }
        __syncthreads();

        #pragma unroll
        for (int ks = 0; ks < 4; ks++) {
            const uint32_t kb = (uint32_t)ks * 32;
            uint32_t ah[2][4], al[2][4];
            #pragma unroll
            for (int mi = 0; mi < 2; mi++) {
                uint32_t row = (uint32_t)(wm * 32 + mi * 16 + (lane & 15));
                uint32_t kby = kb + ((lane >> 4) << 4);
                uint32_t off = (uint32_t)kc * 8192 + row * 128 + (kby ^ ((row & 7) << 4));
                ldsm_x4(ah[mi], sb + S3_XHI + off);
                ldsm_x4(al[mi], sb + S3_XLO + off);
            }
            #pragma unroll
            for (int bj = 0; bj < 4; bj++) {
                uint32_t rown = (uint32_t)(wn * 64 + bj * 16 + (lane & 7) + ((lane >> 4) << 3));
                uint32_t kby  = kb + (((lane >> 3) & 1) << 4);
                uint32_t off  = rown * 128 + (kby ^ ((rown & 7) << 4));
                uint32_t bh[4], bl[4];
                ldsm_x4(bh, sb + S3_WHI + off);
                ldsm_x4(bl, sb + S3_WLO + off);
                #pragma unroll
                for (int mi = 0; mi < 2; mi++) {
                    mma_bf16(acc[mi][bj*2+0], ah[mi], bh[0], bh[1]);
                    mma_bf16(acc[mi][bj*2+0], ah[mi], bl[0], bl[1]);
                    mma_bf16(acc[mi][bj*2+0], al[mi], bh[0], bh[1]);
                    mma_bf16(acc[mi][bj*2+1], ah[mi], bh[2], bh[3]);
                    mma_bf16(acc[mi][bj*2+1], ah[mi], bl[2], bl[3]);
                    mma_bf16(acc[mi][bj*2+1], al[mi], bh[2], bh[3]);
                }
            }
        }
        __syncthreads();
    }

    // ---- gelu + write H tiles (chunk = wn) ----
    {
        #pragma unroll
        for (int mi = 0; mi < 2; mi++) {
            int R0 = wm * 32 + mi * 16 + qr;
            int R1 = R0 + 8;
            #pragma unroll
            for (int nt = 0; nt < 8; nt++) {
                int C = wn * 64 + nt * 8 + qc * 2;
                float h00 = geluf(acc[mi][nt][0] + b1v[C]);
                float h01 = geluf(acc[mi][nt][1] + b1v[C+1]);
                float h10 = geluf(acc[mi][nt][2] + b1v[C]);
                float h11 = geluf(acc[mi][nt][3] + b1v[C+1]);
                uint2 pA = split_pack(h00, h01);
                uint2 pB = split_pack(h10, h11);
                uint32_t base = (uint32_t)wn * 8192;
                uint32_t kloc = (uint32_t)(nt * 16 + qc * 4);
                uint32_t oA = base + (uint32_t)R0 * 128 + (kloc ^ ((R0 & 7) << 4));
                uint32_t oB = base + (uint32_t)R1 * 128 + (kloc ^ ((R1 & 7) << 4));
                *(uint32_t*)(sm3 + S3_HHI + oA) = pA.x;
                *(uint32_t*)(sm3 + S3_HLO + oA) = pA.y;
                *(uint32_t*)(sm3 + S3_HHI + oB) = pB.x;
                *(uint32_t*)(sm3 + S3_HLO + oB) = pB.y;
            }
        }
    }
    __syncthreads();

    // ---- GEMM2: O[64x128] = H[64x256] @ W2 ----
    float acc2[2][4][4];
    #pragma unroll
    for (int mi = 0; mi < 2; mi++)
        #pragma unroll
        for (int nt = 0; nt < 4; nt++)
            #pragma unroll
            for (int j = 0; j < 4; j++) acc2[mi][nt][j] = 0.f;

    for (int kc = 0; kc < 4; kc++) {
        #pragma unroll 4
        for (int i = 0; i < 16; i++) {
            int idx = t + i * 256;
            int kpl = idx & 31, nl = idx >> 5;
            uint2 w = g_w2p[nl * 128 + kc * 32 + kpl];
            uint32_t off = (uint32_t)nl * 128 + (((uint32_t)kpl * 4) ^ ((nl & 7) << 4));
            *(uint32_t*)(sm3 + S3_WHI + off) = w.x;
            *(uint32_t*)(sm3 + S3_WLO + off) = w.y;
        }
        __syncthreads();

        #pragma unroll
        for (int ks = 0; ks < 4; ks++) {
            const uint32_t kb = (uint32_t)ks * 32;
            uint32_t ah[2][4], al[2][4];
            #pragma unroll
            for (int mi = 0; mi < 2; mi++) {
                uint32_t row = (uint32_t)(wm * 32 + mi * 16 + (lane & 15));
                uint32_t kby = kb + ((lane >> 4) << 4);
                uint32_t off = (uint32_t)kc * 8192 + row * 128 + (kby ^ ((row & 7) << 4));
                ldsm_x4(ah[mi], sb + S3_HHI + off);
                ldsm_x4(al[mi], sb + S3_HLO + off);
            }
            #pragma unroll
            for (int bj = 0; bj < 2; bj++) {
                uint32_t rown = (uint32_t)(wn * 32 + bj * 16 + (lane & 7) + ((lane >> 4) << 3));
                uint32_t kby  = kb + (((lane >> 3) & 1) << 4);
                uint32_t off  = rown * 128 + (kby ^ ((rown & 7) << 4));
                uint32_t bh[4], bl[4];
                ldsm_x4(bh, sb + S3_WHI + off);
                ldsm_x4(bl, sb + S3_WLO + off);
                #pragma unroll
                for (int mi = 0; mi < 2; mi++) {
                    mma_bf16(acc2[mi][bj*2+0], ah[mi], bh[0], bh[1]);
                    mma_bf16(acc2[mi][bj*2+0], ah[mi], bl[0], bl[1]);
                    mma_bf16(acc2[mi][bj*2+0], al[mi], bh[0], bh[1]);
                    mma_bf16(acc2[mi][bj*2+1], ah[mi], bh[2], bh[3]);
                    mma_bf16(acc2[mi][bj*2+1], ah[mi], bl[2], bl[3]);
                    mma_bf16(acc2[mi][bj*2+1], al[mi], bh[2], bh[3]);
                }
            }
        }
        __syncthreads();
    }

    // ---- epilogue: residual + bias ----
    float* outstage = (float*)(sm3 + S3_WHI);
    {
        #pragma unroll
        for (int mi = 0; mi < 2; mi++) {
            #pragma unroll
            for (int nt = 0; nt < 4; nt++) {
                int C = wn * 32 + nt * 8 + qc * 2;
                float bC0 = b2v[C], bC1 = b2v[C+1];
                #pragma unroll
                for (int rh = 0; rh < 2; rh++) {
                    int R = wm * 32 + mi * 16 + qr + rh * 8;
                    uint32_t off = (uint32_t)(C >> 6) * 8192 + (uint32_t)R * 128 +
                                   ((((uint32_t)(C & 63)) * 2) ^ ((R & 7) << 4));
                    uint32_t xh = *(uint32_t*)(sm3 + S3_XHI + off);
                    uint32_t xl = *(uint32_t*)(sm3 + S3_XLO + off);
                    float r0 = bflo_f(xh) + bflo_f(xl);
                    float r1 = bfhi_f(xh) + bfhi_f(xl);
                    outstage[R * OS_STRIDE + C]     = r0 + acc2[mi][nt][rh*2+0] + bC0;
                    outstage[R * OS_STRIDE + C + 1] = r1 + acc2[mi][nt][rh*2+1] + bC1;
                }
            }
        }
    }
    __syncthreads();

    // ---- LN2 ----
    #pragma unroll
    for (int k = 0; k < 8; k++) {
        int pp = wid * 8 + k;
        float v0 = outstage[pp*OS_STRIDE + lane];
        float v1 = outstage[pp*OS_STRIDE + lane + 32];
        float v2 = outstage[pp*OS_STRIDE + lane + 64];
        float v3 = outstage[pp*OS_STRIDE + lane + 96];
        float s  = wred(v0+v1+v2+v3);
        float s2 = wred(v0*v0+v1*v1+v2*v2+v3*v3);
        float mu = s * (1.f/128.f);
        float var = s2 * (1.f/128.f) - mu*mu;
        float rs = rsqrtf(var + 1e-5f);
        outstage[pp*OS_STRIDE + lane]      = (v0-mu)*rs*l2g[lane]    + l2b[lane];
        outstage[pp*OS_STRIDE + lane + 32] = (v1-mu)*rs*l2g[lane+32] + l2b[lane+32];
        outstage[pp*OS_STRIDE + lane + 64] = (v2-mu)*rs*l2g[lane+64] + l2b[lane+64];
        outstage[pp*OS_STRIDE + lane + 96] = (v3-mu)*rs*l2g[lane+96] + l2b[lane+96];
    }
    __syncthreads();

    // ---- transposed store ----
    for (int i = t; i < 64 * DDIM; i += 256) {
        int d = i >> 6, pp = i & 63;
        out[((size_t)b * DDIM + d) * PP + p0 + pp] = outstage[pp * OS_STRIDE + d];
    }
}

// ---------------------------------------------------------------------------
extern "C" void kernel_launch(void* const* d_in, const int* in_sizes, int n_in,
                              void* d_out, int out_size)
{
    const float* feature   = (const float*)d_in[0];
    const float* I_src     = (const float*)d_in[1];
    const float* I_tar_inv = (const float*)d_in[2];
    const float* E         = (const float*)d_in[3];
    const float* dis       = (const float*)d_in[4];
    const float* norm_vec  = (const float*)d_in[5];
    const float* bn_gamma  = (const float*)d_in[6];
    const float* bn_beta   = (const float*)d_in[7];
    const float* bn_mean   = (const float*)d_in[8];
    const float* bn_var    = (const float*)d_in[9];
    const float* conv_w    = (const float*)d_in[10];
    const float* ln1_g     = (const float*)d_in[11];
    const float* ln1_b     = (const float*)d_in[12];
    const float* mlp_w1    = (const float*)d_in[13];
    const float* mlp_b1    = (const float*)d_in[14];
    const float* mlp_w2    = (const float*)d_in[15];
    const float* mlp_b2    = (const float*)d_in[16];
    const float* ln2_g     = (const float*)d_in[17];
    const float* ln2_b     = (const float*)d_in[18];
    float* out = (float*)d_out;

    cudaFuncSetAttribute(k1_conv_tc,
                         cudaFuncAttributeMaxDynamicSharedMemorySize, K1_SMEM);
    cudaFuncSetAttribute(k3_mlp_tc,
                         cudaFuncAttributeMaxDynamicSharedMemorySize, K3T_SMEM);

    k0_prep<<<1, 256>>>(I_src, I_tar_inv, E, dis, norm_vec,
                        bn_gamma, bn_beta, bn_mean, bn_var);
    k0b1_pack<<<64, 256>>>(conv_w);
    k0b2_pack<<<64, 256>>>(mlp_w1, mlp_w2);
    k1_conv_tc<<<dim3(PP/128, BN), 256, K1_SMEM>>>(feature);
    k2_attn<<<dim3(PP/8, BB), 256>>>();
    k3_mlp_tc<<<dim3(PP/64, BB), 256, K3T_SMEM>>>(ln1_g, ln1_b, mlp_b1, mlp_b2,
                                                  ln2_g, ln2_b, out);
}

// round 16
// speedup vs baseline: 1.1342x; 1.0410x over previous
#include <cuda_runtime.h>
#include <cuda_bf16.h>
#include <math.h>
#include <stdint.h>

// Problem constants
#define BB 4
#define NN 6
#define FDIM 256
#define DDIM 128
#define HH 64
#define WW 120
#define PP (HH*WW)          // 7680
#define BN (BB*NN)          // 24
#define IMG_H 480.0f
#define IMG_W 960.0f

// Scratch (device globals — no runtime allocation allowed)
__device__ float g_val[(size_t)BN * PP * DDIM];   // (bn, p, d)  94.4 MB
__device__ float g_z[(size_t)BB * PP * DDIM];     // (b, p, d)   15.7 MB
__device__ float g_Hm[BN * 9];
__device__ float g_bnscale[FDIM];
__device__ float g_bnshift[FDIM];
// Prepacked split-bf16 weights
__device__ uint32_t g_wch[128 * 128];  // conv_w hi pairs [d][kpair]
__device__ uint32_t g_wcl[128 * 128];  // conv_w lo pairs
__device__ uint2 g_w1p[256 * 64];      // W1^T  [n=256][kpair=64]
__device__ uint2 g_w2p[128 * 128];     // W2^T  [n=128][kpair=128]

// ===========================================================================
// helpers: sm_80-baseline tensor path (ldmatrix + mma.sync) — no 'a' features
// ===========================================================================
__device__ __forceinline__ uint32_t smem_u32(const void* p) {
    uint32_t a;
    asm("{ .reg .u64 t; cvta.to.shared.u64 t, %1; cvt.u32.u64 %0, t; }"
        : "=r"(a) : "l"(p));
    return a;
}
__device__ __forceinline__ void ldsm_x4(uint32_t* r, uint32_t addr) {
    asm volatile("ldmatrix.sync.aligned.m8n8.x4.shared.b16 {%0,%1,%2,%3}, [%4];"
        : "=r"(r[0]), "=r"(r[1]), "=r"(r[2]), "=r"(r[3]) : "r"(addr));
}
__device__ __forceinline__ void mma_bf16(float* c, const uint32_t* a,
                                         uint32_t b0, uint32_t b1) {
    asm volatile(
        "mma.sync.aligned.m16n8k16.row.col.f32.bf16.bf16.f32 "
        "{%0,%1,%2,%3}, {%4,%5,%6,%7}, {%8,%9}, {%0,%1,%2,%3};"
        : "+f"(c[0]), "+f"(c[1]), "+f"(c[2]), "+f"(c[3])
        : "r"(a[0]), "r"(a[1]), "r"(a[2]), "r"(a[3]), "r"(b0), "r"(b1));
}
__device__ __forceinline__ void cp_async16(uint32_t smem_addr, const void* gptr) {
    asm volatile("cp.async.ca.shared.global [%0], [%1], 16;"
        :: "r"(smem_addr), "l"(gptr) : "memory");
}
__device__ __forceinline__ uint32_t pack_bf16x2(__nv_bfloat16 lo, __nv_bfloat16 hi) {
    return ((uint32_t)__bfloat16_as_ushort(hi) << 16) | __bfloat16_as_ushort(lo);
}
__device__ __forceinline__ uint2 split_pack(float a, float b) {
    __nv_bfloat16 ha = __float2bfloat16(a), hb = __float2bfloat16(b);
    __nv_bfloat16 la = __float2bfloat16(a - __bfloat162float(ha));
    __nv_bfloat16 lb = __float2bfloat16(b - __bfloat162float(hb));
    return make_uint2(pack_bf16x2(ha, hb), pack_bf16x2(la, lb));
}
__device__ __forceinline__ float bflo_f(uint32_t u) { return __uint_as_float(u << 16); }
__device__ __forceinline__ float bfhi_f(uint32_t u) { return __uint_as_float(u & 0xffff0000u); }
__device__ __forceinline__ float geluf(float h) {
    return 0.5f * h * (1.f + erff(h * 0.70710678118654752f));
}
__device__ __forceinline__ float wred(float v) {
    #pragma unroll
    for (int o = 16; o; o >>= 1) v += __shfl_xor_sync(0xffffffffu, v, o);
    return v;
}

// ---------------------------------------------------------------------------
// K0: homographies + BN scale/shift
// ---------------------------------------------------------------------------
__global__ void k0_prep(const float* __restrict__ I_src,
                        const float* __restrict__ I_tar_inv,
                        const float* __restrict__ E,
                        const float* __restrict__ disp,
                        const float* __restrict__ nvec,
                        const float* __restrict__ bng,
                        const float* __restrict__ bnb,
                        const float* __restrict__ bnm,
                        const float* __restrict__ bnv)
{
    int t = threadIdx.x;
    if (t < FDIM) {
        float sc = bng[t] * rsqrtf(bnv[t] + 1e-5f);
        g_bnscale[t] = sc;
        g_bnshift[t] = bnb[t] - bnm[t] * sc;
    }
    if (t < BN) {
        int b = t / NN;
        float dis = disp[0];
        const float* Eb = E + t * 16;
        const float* Ks = I_src + t * 9;
        const float* Kt = I_tar_inv + b * 9;
        float nv0 = nvec[b*3+0], nv1 = nvec[b*3+1], nv2 = nvec[b*3+2];
        float A[9];
        #pragma unroll
        for (int i = 0; i < 3; i++) {
            float Ti = Eb[i*4+3] / dis;
            A[i*3+0] = Eb[i*4+0] - Ti * nv0;
            A[i*3+1] = Eb[i*4+1] - Ti * nv1;
            A[i*3+2] = Eb[i*4+2] - Ti * nv2;
        }
        float M[9];
        #pragma unroll
        for (int i = 0; i < 3; i++)
            #pragma unroll
            for (int j = 0; j < 3; j++)
                M[i*3+j] = Ks[i*3+0]*A[0*3+j] + Ks[i*3+1]*A[1*3+j] + Ks[i*3+2]*A[2*3+j];
        #pragma unroll
        for (int i = 0; i < 3; i++)
            #pragma unroll
            for (int j = 0; j < 3; j++)
                g_Hm[t*9 + i*3+j] = M[i*3+0]*Kt[0*3+j] + M[i*3+1]*Kt[1*3+j] + M[i*3+2]*Kt[2*3+j];
    }
}

// ---------------------------------------------------------------------------
// K0b1: pack conv_w split-bf16 hi/lo pair arrays
// ---------------------------------------------------------------------------
__global__ void k0b1_pack(const float* __restrict__ Wc)
{
    int i = blockIdx.x * 256 + threadIdx.x;   // 0..16383
    int d = i >> 7, fp = i & 127;
    uint2 p = split_pack(Wc[d*256 + fp*2], Wc[d*256 + fp*2 + 1]);
    g_wch[i] = p.x;
    g_wcl[i] = p.y;
}

// ---------------------------------------------------------------------------
// K0b2: pack W1^T / W2^T split-bf16 pair arrays
// ---------------------------------------------------------------------------
__global__ void k0b2_pack(const float* __restrict__ W1,
                          const float* __restrict__ W2)
{
    int i = blockIdx.x * 256 + threadIdx.x;   // 0..16383
    {   // W2^T: g_w2p[n=d][kpair over j], W2 is [256 j][128 d]
        int d = i >> 7, kp = i & 127;
        g_w2p[i] = split_pack(W2[(kp*2)*128 + d], W2[(kp*2+1)*128 + d]);
    }
    {   // W1^T: g_w1p[n=j][kpair over d], W1 is [128 d][256 j]
        int j = i >> 6, kp = i & 63;
        g_w1p[i] = split_pack(W1[(kp*2)*256 + j], W1[(kp*2+1)*256 + j]);
    }
}

// ---------------------------------------------------------------------------
// K1 (HMMA, 512 threads / 16 warps, 2-stage pipelined, term-major):
// val[bn][p][d] = sum_f W[d][f]*relu(bn(feat))
// CTA tile 128px(M) x 128d(N), warp tile 32x32 (wm, wn in 0..3).
// K-chunks of 64, double-buffered smem (128 KB). X reg-prefetch + convert
// after MMAs; W via cp.async from prepacked arrays.
// ---------------------------------------------------------------------------
#define K1_SMEM 131072

__global__ void __launch_bounds__(512)
k1_conv_tc(const float* __restrict__ feat)
{
    extern __shared__ char smem[];
    const uint32_t sb = smem_u32(smem);
    const int bn = blockIdx.y;
    const int p0 = blockIdx.x * 128;
    const int t  = threadIdx.x;
    const int wid = t >> 5, lane = t & 31;
    const int wm = wid & 3;    // M quarter (rows wm*32..+31)
    const int wn = wid >> 2;   // N quarter (cols wn*32..+31)
    const int pl  = t & 127;   // X producer: pixel row
    const int fp0 = t >> 7;    // kpair phase 0..3

    float acc[2][4][4];
    #pragma unroll
    for (int mi = 0; mi < 2; mi++)
        #pragma unroll
        for (int nt = 0; nt < 4; nt++)
            #pragma unroll
            for (int j = 0; j < 4; j++) acc[mi][nt][j] = 0.f;

    const float* fb = feat + (size_t)bn * FDIM * PP + p0;

    // ---- prologue: stage 0 = chunk 0 ----
    #pragma unroll
    for (int i = 0; i < 2; i++) {           // W chunk 0 via cp.async
        int idx = t + i * 512;              // 16B-unit 0..1023
        int kq = idx & 7, dl = idx >> 3;
        uint32_t off = (uint32_t)dl * 128 + (((uint32_t)kq * 16) ^ ((dl & 7) << 4));
        cp_async16(sb + 65536 + off,          g_wch + dl * 128 + kq * 4);
        cp_async16(sb + 65536 + 16384 + off,  g_wcl + dl * 128 + kq * 4);
    }
    asm volatile("cp.async.commit_group;" ::: "memory");
    #pragma unroll
    for (int i = 0; i < 8; i++) {           // X chunk 0 direct
        int fp = fp0 + 4 * i;               // kpair 0..31
        int f  = 2 * fp;
        float v0 = fb[(size_t)f       * PP + pl];
        float v1 = fb[(size_t)(f + 1) * PP + pl];
        v0 = fmaxf(fmaf(v0, g_bnscale[f],   g_bnshift[f]),   0.f);
        v1 = fmaxf(fmaf(v1, g_bnscale[f+1], g_bnshift[f+1]), 0.f);
        uint2 p = split_pack(v0, v1);
        uint32_t off = (uint32_t)pl * 128 + (((uint32_t)fp * 4) ^ ((pl & 7) << 4));
        *(uint32_t*)(smem + off)         = p.x;
        *(uint32_t*)(smem + 16384 + off) = p.y;
    }

    for (int c = 0; c < 4; c++) {
        const int s = c & 1;
        const uint32_t xbase = sb + (uint32_t)s * 32768;
        const uint32_t wbase = sb + 65536 + (uint32_t)s * 32768;

        // prefetch next chunk's X into registers (latency hidden by MMAs)
        float v0r[8], v1r[8];
        if (c < 3) {
            const int f0n = (c + 1) * 64;
            #pragma unroll
            for (int i = 0; i < 8; i++) {
                int f = f0n + 2 * (fp0 + 4 * i);
                v0r[i] = fb[(size_t)f       * PP + pl];
                v1r[i] = fb[(size_t)(f + 1) * PP + pl];
            }
        }

        asm volatile("cp.async.wait_group 0;" ::: "memory");
        __syncthreads();   // stage s fully ready; stage s^1 free

        // issue W cp.async for chunk c+1 into stage s^1 (overlaps MMAs)
        if (c < 3) {
            const uint32_t wb1 = sb + 65536 + (uint32_t)(s ^ 1) * 32768;
            #pragma unroll
            for (int i = 0; i < 2; i++) {
                int idx = t + i * 512;
                int kq = idx & 7, dl = idx >> 3;
                uint32_t off = (uint32_t)dl * 128 + (((uint32_t)kq * 16) ^ ((dl & 7) << 4));
                cp_async16(wb1 + off,         g_wch + dl * 128 + (c + 1) * 32 + kq * 4);
                cp_async16(wb1 + 16384 + off, g_wcl + dl * 128 + (c + 1) * 32 + kq * 4);
            }
            asm volatile("cp.async.commit_group;" ::: "memory");
        }

        // ---- MMAs on stage s ----
        #pragma unroll
        for (int ks = 0; ks < 4; ks++) {
            const uint32_t kb = (uint32_t)ks * 32;
            uint32_t ah[2][4], al[2][4];
            #pragma unroll
            for (int mi = 0; mi < 2; mi++) {
                uint32_t row = (uint32_t)(wm * 32 + mi * 16 + (lane & 15));
                uint32_t kby = kb + ((lane >> 4) << 4);
                uint32_t off = row * 128 + (kby ^ ((row & 7) << 4));
                ldsm_x4(ah[mi], xbase + off);
                ldsm_x4(al[mi], xbase + 16384 + off);
            }
            uint32_t bh[2][4], bl[2][4];
            #pragma unroll
            for (int bj = 0; bj < 2; bj++) {
                uint32_t rown = (uint32_t)(wn * 32 + bj * 16 + (lane & 7) + ((lane >> 4) << 3));
                uint32_t kby  = kb + (((lane >> 3) & 1) << 4);
                uint32_t off  = rown * 128 + (kby ^ ((rown & 7) << 4));
                ldsm_x4(bh[bj], wbase + off);
                ldsm_x4(bl[bj], wbase + 16384 + off);
            }
            // term-major: hh -> hl -> lh (8 independent MMAs between acc reuse)
            #pragma unroll
            for (int bj = 0; bj < 2; bj++)
                #pragma unroll
                for (int mi = 0; mi < 2; mi++) {
                    mma_bf16(acc[mi][bj*2+0], ah[mi], bh[bj][0], bh[bj][1]);
                    mma_bf16(acc[mi][bj*2+1], ah[mi], bh[bj][2], bh[bj][3]);
                }
            #pragma unroll
            for (int bj = 0; bj < 2; bj++)
                #pragma unroll
                for (int mi = 0; mi < 2; mi++) {
                    mma_bf16(acc[mi][bj*2+0], ah[mi], bl[bj][0], bl[bj][1]);
                    mma_bf16(acc[mi][bj*2+1], ah[mi], bl[bj][2], bl[bj][3]);
                }
            #pragma unroll
            for (int bj = 0; bj < 2; bj++)
                #pragma unroll
                for (int mi = 0; mi < 2; mi++) {
                    mma_bf16(acc[mi][bj*2+0], al[mi], bh[bj][0], bh[bj][1]);
                    mma_bf16(acc[mi][bj*2+1], al[mi], bh[bj][2], bh[bj][3]);
                }
        }

        // ---- convert prefetched X -> stage s^1 ----
        if (c < 3) {
            const int f0n = (c + 1) * 64;
            char* xdst = smem + (size_t)(s ^ 1) * 32768;
            #pragma unroll
            for (int i = 0; i < 8; i++) {
                int fp = fp0 + 4 * i;
                int f  = f0n + 2 * fp;
                float v0 = fmaxf(fmaf(v0r[i], g_bnscale[f],   g_bnshift[f]),   0.f);
                float v1 = fmaxf(fmaf(v1r[i], g_bnscale[f+1], g_bnshift[f+1]), 0.f);
                uint2 p = split_pack(v0, v1);
                uint32_t off = (uint32_t)pl * 128 + (((uint32_t)fp * 4) ^ ((pl & 7) << 4));
                *(uint32_t*)(xdst + off)         = p.x;
                *(uint32_t*)(xdst + 16384 + off) = p.y;
            }
        }
    }

    // epilogue: D fragments -> g_val (each warp: 32x32 block)
    const int qr = lane >> 2, qc = lane & 3;
    #pragma unroll
    for (int mi = 0; mi < 2; mi++) {
        int row0 = p0 + wm * 32 + mi * 16 + qr;
        float* r0 = g_val + ((size_t)bn * PP + row0) * DDIM;
        float* r1 = r0 + 8 * DDIM;
        #pragma unroll
        for (int nt = 0; nt < 4; nt++) {
            int col = wn * 32 + nt * 8 + qc * 2;
            *(float2*)(r0 + col) = make_float2(acc[mi][nt][0], acc[mi][nt][1]);
            *(float2*)(r1 + col) = make_float2(acc[mi][nt][2], acc[mi][nt][3]);
        }
    }
}

// ---------------------------------------------------------------------------
// K2: homography + bilinear sample + normalized dot + softmax + weighted sum
// ---------------------------------------------------------------------------
__global__ void __launch_bounds__(256) k2_attn()
{
    int b    = blockIdx.y;
    int p    = blockIdx.x * 8 + (threadIdx.x >> 5);
    int lane = threadIdx.x & 31;

    int col = p % WW, row = p / WW;
    float pxc = (float)col * (IMG_W / (float)(WW - 1));
    float pyc = (float)row * (IMG_H / (float)(HH - 1));

    const float4* qptr = (const float4*)(g_val + ((size_t)(b*NN + 0) * PP + p) * DDIM);
    float4 q4 = qptr[lane];
    float qss = wred(q4.x*q4.x + q4.y*q4.y + q4.z*q4.z + q4.w*q4.w);
    float qinv = 1.f / fmaxf(sqrtf(qss), 1e-12f);

    float4 s4[NN];
    float dotv[NN];

    #pragma unroll
    for (int n = 0; n < NN; n++) {
        const float* H = g_Hm + (b*NN + n) * 9;
        float hz = fmaf(H[6], pxc, fmaf(H[7], pyc, H[8]));
        float hx = fmaf(H[0], pxc, fmaf(H[1], pyc, H[2])) / hz;
        float hy = fmaf(H[3], pxc, fmaf(H[4], pyc, H[5])) / hz;
        float sx = hx * ((float)WW / IMG_W);
        float sy = hy * ((float)HH / IMG_H);
        bool valid = (sx >= 0.f) && (sx <= (float)(WW-1)) &&
                     (sy >= 0.f) && (sy <= (float)(HH-1));
        sx = fminf(fmaxf(sx, -1e4f), 1e4f);
        sy = fminf(fmaxf(sy, -1e4f), 1e4f);
        float x0f = floorf(sx), y0f = floorf(sy);
        int   x0 = (int)x0f,    y0 = (int)y0f;
        float fx = sx - x0f, fy = sy - y0f;

        float4 acc = make_float4(0.f, 0.f, 0.f, 0.f);
        const float* vb = g_val + (size_t)(b*NN + n) * PP * DDIM;
        #pragma unroll
        for (int c = 0; c < 4; c++) {
            int cx = x0 + (c & 1);
            int cy = y0 + (c >> 1);
            float wx = (c & 1)  ? fx : 1.f - fx;
            float wy = (c >> 1) ? fy : 1.f - fy;
            if (cx >= 0 && cx < WW && cy >= 0 && cy < HH) {
                const float4* vp = (const float4*)(vb + ((size_t)(cy*WW + cx)) * DDIM) + lane;
                float4 v = *vp;
                float w = wx * wy;
                acc.x = fmaf(w, v.x, acc.x);
                acc.y = fmaf(w, v.y, acc.y);
                acc.z = fmaf(w, v.z, acc.z);
                acc.w = fmaf(w, v.w, acc.w);
            }
        }
        s4[n] = acc;
        float ss = acc.x*acc.x + acc.y*acc.y + acc.z*acc.z + acc.w*acc.w;
        float dd = q4.x*acc.x + q4.y*acc.y + q4.z*acc.z + q4.w*acc.w;
        #pragma unroll
        for (int o = 16; o; o >>= 1) {
            ss += __shfl_xor_sync(0xffffffffu, ss, o);
            dd += __shfl_xor_sync(0xffffffffu, dd, o);
        }
        float sinv = 1.f / fmaxf(sqrtf(ss), 1e-12f);
        dotv[n] = valid ? dd * qinv * sinv : 0.f;
    }

    float m = dotv[0];
    #pragma unroll
    for (int n = 1; n < NN; n++) m = fmaxf(m, dotv[n]);
    float e[NN], se = 0.f;
    #pragma unroll
    for (int n = 0; n < NN; n++) { e[n] = expf(dotv[n] - m); se += e[n]; }
    float inv = 1.f / se;

    float4 o = q4;
    #pragma unroll
    for (int n = 0; n < NN; n++) {
        float a = e[n] * inv;
        o.x = fmaf(a, s4[n].x, o.x);
        o.y = fmaf(a, s4[n].y, o.y);
        o.z = fmaf(a, s4[n].z, o.z);
        o.w = fmaf(a, s4[n].w, o.w);
    }
    float4* zp = (float4*)(g_z + ((size_t)b * PP + p) * DDIM);
    zp[lane] = o;
}

// ---------------------------------------------------------------------------
// K3 (HMMA): LN1 -> GEMM1(64x256x128) -> gelu -> GEMM2(64x128x256)
//            -> residual(LN1 out) -> LN2 -> transposed store
// ---------------------------------------------------------------------------
#define S3_XHI 0
#define S3_XLO 16384
#define S3_WHI 32768
#define S3_WLO 65536
#define S3_HHI 98304
#define S3_HLO 131072
#define K3T_SMEM 163840
#define OS_STRIDE 132

__global__ void __launch_bounds__(256)
k3_mlp_tc(const float* __restrict__ l1g, const float* __restrict__ l1b,
          const float* __restrict__ b1v, const float* __restrict__ b2v,
          const float* __restrict__ l2g, const float* __restrict__ l2b,
          float* __restrict__ out)
{
    extern __shared__ char sm3[];
    const uint32_t sb = smem_u32(sm3);
    const int b  = blockIdx.y;
    const int p0 = blockIdx.x * 64;
    const int t  = threadIdx.x;
    const int lane = t & 31, wid = t >> 5;

    // ---- Phase 0: load z, LN1, write X hi/lo tiles ----
    {
        const float* zb = g_z + ((size_t)b * PP + p0) * DDIM;
        float4 g  = *(const float4*)(l1g + lane * 4);
        float4 be = *(const float4*)(l1b + lane * 4);
        #pragma unroll
        for (int rr = 0; rr < 8; rr++) {
            int row = wid * 8 + rr;
            float4 v = *(const float4*)(zb + (size_t)row * DDIM + lane * 4);
            float s  = wred(v.x + v.y + v.z + v.w);
            float s2 = wred(v.x*v.x + v.y*v.y + v.z*v.z + v.w*v.w);
            float mu = s * (1.f/128.f);
            float var = s2 * (1.f/128.f) - mu*mu;
            float rs = rsqrtf(var + 1e-5f);
            float x0 = (v.x - mu) * rs * g.x + be.x;
            float x1 = (v.y - mu) * rs * g.y + be.y;
            float x2 = (v.z - mu) * rs * g.z + be.z;
            float x3 = (v.w - mu) * rs * g.w + be.w;
            uint2 pA = split_pack(x0, x1);
            uint2 pB = split_pack(x2, x3);
            uint32_t base = (uint32_t)(lane >> 4) * 8192 + (uint32_t)row * 128;
            uint32_t o0 = base + ((((lane & 15) * 8) + 0) ^ ((row & 7) << 4));
            uint32_t o1 = base + ((((lane & 15) * 8) + 4) ^ ((row & 7) << 4));
            *(uint32_t*)(sm3 + S3_XHI + o0) = pA.x;
            *(uint32_t*)(sm3 + S3_XLO + o0) = pA.y;
            *(uint32_t*)(sm3 + S3_XHI + o1) = pB.x;
            *(uint32_t*)(sm3 + S3_XLO + o1) = pB.y;
        }
    }
    __syncthreads();

    const int wm = wid & 1;
    const int wn = wid >> 1;
    const int qr = lane >> 2, qc = lane & 3;

    // ---- GEMM1: H[64x256] = X[64x128] @ W1 ----
    float acc[2][8][4];
    #pragma unroll
    for (int mi = 0; mi < 2; mi++)
        #pragma unroll
        for (int nt = 0; nt < 8; nt++)
            #pragma unroll
            for (int j = 0; j < 4; j++) acc[mi][nt][j] = 0.f;

    for (int kc = 0; kc < 2; kc++) {
        #pragma unroll 4
        for (int i = 0; i < 32; i++) {
            int idx = t + i * 256;
            int kpl = idx & 31, nl = idx >> 5;
            uint2 w = g_w1p[nl * 64 + kc * 32 + kpl];
            uint32_t off = (uint32_t)nl * 128 + (((uint32_t)kpl * 4) ^ ((nl & 7) << 4));
            *(uint32_t*)(sm3 + S3_WHI + off) = w.x;
            *(uint32_t*)(sm3 + S3_WLO + off) = w.y;
        }
        __syncthreads();

        #pragma unroll
        for (int ks = 0; ks < 4; ks++) {
            const uint32_t kb = (uint32_t)ks * 32;
            uint32_t ah[2][4], al[2][4];
            #pragma unroll
            for (int mi = 0; mi < 2; mi++) {
                uint32_t row = (uint32_t)(wm * 32 + mi * 16 + (lane & 15));
                uint32_t kby = kb + ((lane >> 4) << 4);
                uint32_t off = (uint32_t)kc * 8192 + row * 128 + (kby ^ ((row & 7) << 4));
                ldsm_x4(ah[mi], sb + S3_XHI + off);
                ldsm_x4(al[mi], sb + S3_XLO + off);
            }
            #pragma unroll
            for (int bj = 0; bj < 4; bj++) {
                uint32_t rown = (uint32_t)(wn * 64 + bj * 16 + (lane & 7) + ((lane >> 4) << 3));
                uint32_t kby  = kb + (((lane >> 3) & 1) << 4);
                uint32_t off  = rown * 128 + (kby ^ ((rown & 7) << 4));
                uint32_t bh[4], bl[4];
                ldsm_x4(bh, sb + S3_WHI + off);
                ldsm_x4(bl, sb + S3_WLO + off);
                #pragma unroll
                for (int mi = 0; mi < 2; mi++) {
                    mma_bf16(acc[mi][bj*2+0], ah[mi], bh[0], bh[1]);
                    mma_bf16(acc[mi][bj*2+0], ah[mi], bl[0], bl[1]);
                    mma_bf16(acc[mi][bj*2+0], al[mi], bh[0], bh[1]);
                    mma_bf16(acc[mi][bj*2+1], ah[mi], bh[2], bh[3]);
                    mma_bf16(acc[mi][bj*2+1], ah[mi], bl[2], bl[3]);
                    mma_bf16(acc[mi][bj*2+1], al[mi], bh[2], bh[3]);
                }
            }
        }
        __syncthreads();
    }

    // ---- gelu + write H tiles (chunk = wn) ----
    {
        #pragma unroll
        for (int mi = 0; mi < 2; mi++) {
            int R0 = wm * 32 + mi * 16 + qr;
            int R1 = R0 + 8;
            #pragma unroll
            for (int nt = 0; nt < 8; nt++) {
                int C = wn * 64 + nt * 8 + qc * 2;
                float h00 = geluf(acc[mi][nt][0] + b1v[C]);
                float h01 = geluf(acc[mi][nt][1] + b1v[C+1]);
                float h10 = geluf(acc[mi][nt][2] + b1v[C]);
                float h11 = geluf(acc[mi][nt][3] + b1v[C+1]);
                uint2 pA = split_pack(h00, h01);
                uint2 pB = split_pack(h10, h11);
                uint32_t base = (uint32_t)wn * 8192;
                uint32_t kloc = (uint32_t)(nt * 16 + qc * 4);
                uint32_t oA = base + (uint32_t)R0 * 128 + (kloc ^ ((R0 & 7) << 4));
                uint32_t oB = base + (uint32_t)R1 * 128 + (kloc ^ ((R1 & 7) << 4));
                *(uint32_t*)(sm3 + S3_HHI + oA) = pA.x;
                *(uint32_t*)(sm3 + S3_HLO + oA) = pA.y;
                *(uint32_t*)(sm3 + S3_HHI + oB) = pB.x;
                *(uint32_t*)(sm3 + S3_HLO + oB) = pB.y;
            }
        }
    }
    __syncthreads();

    // ---- GEMM2: O[64x128] = H[64x256] @ W2 ----
    float acc2[2][4][4];
    #pragma unroll
    for (int mi = 0; mi < 2; mi++)
        #pragma unroll
        for (int nt = 0; nt < 4; nt++)
            #pragma unroll
            for (int j = 0; j < 4; j++) acc2[mi][nt][j] = 0.f;

    for (int kc = 0; kc < 4; kc++) {
        #pragma unroll 4
        for (int i = 0; i < 16; i++) {
            int idx = t + i * 256;
            int kpl = idx & 31, nl = idx >> 5;
            uint2 w = g_w2p[nl * 128 + kc * 32 + kpl];
            uint32_t off = (uint32_t)nl * 128 + (((uint32_t)kpl * 4) ^ ((nl & 7) << 4));
            *(uint32_t*)(sm3 + S3_WHI + off) = w.x;
            *(uint32_t*)(sm3 + S3_WLO + off) = w.y;
        }
        __syncthreads();

        #pragma unroll
        for (int ks = 0; ks < 4; ks++) {
            const uint32_t kb = (uint32_t)ks * 32;
            uint32_t ah[2][4], al[2][4];
            #pragma unroll
            for (int mi = 0; mi < 2; mi++) {
                uint32_t row = (uint32_t)(wm * 32 + mi * 16 + (lane & 15));
                uint32_t kby = kb + ((lane >> 4) << 4);
                uint32_t off = (uint32_t)kc * 8192 + row * 128 + (kby ^ ((row & 7) << 4));
                ldsm_x4(ah[mi], sb + S3_HHI + off);
                ldsm_x4(al[mi], sb + S3_HLO + off);
            }
            #pragma unroll
            for (int bj = 0; bj < 2; bj++) {
                uint32_t rown = (uint32_t)(wn * 32 + bj * 16 + (lane & 7) + ((lane >> 4) << 3));
                uint32_t kby  = kb + (((lane >> 3) & 1) << 4);
                uint32_t off  = rown * 128 + (kby ^ ((rown & 7) << 4));
                uint32_t bh[4], bl[4];
                ldsm_x4(bh, sb + S3_WHI + off);
                ldsm_x4(bl, sb + S3_WLO + off);
                #pragma unroll
                for (int mi = 0; mi < 2; mi++) {
                    mma_bf16(acc2[mi][bj*2+0], ah[mi], bh[0], bh[1]);
                    mma_bf16(acc2[mi][bj*2+0], ah[mi], bl[0], bl[1]);
                    mma_bf16(acc2[mi][bj*2+0], al[mi], bh[0], bh[1]);
                    mma_bf16(acc2[mi][bj*2+1], ah[mi], bh[2], bh[3]);
                    mma_bf16(acc2[mi][bj*2+1], ah[mi], bl[2], bl[3]);
                    mma_bf16(acc2[mi][bj*2+1], al[mi], bh[2], bh[3]);
                }
            }
        }
        __syncthreads();
    }

    // ---- epilogue: residual + bias ----
    float* outstage = (float*)(sm3 + S3_WHI);
    {
        #pragma unroll
        for (int mi = 0; mi < 2; mi++) {
            #pragma unroll
            for (int nt = 0; nt < 4; nt++) {
                int C = wn * 32 + nt * 8 + qc * 2;
                float bC0 = b2v[C], bC1 = b2v[C+1];
                #pragma unroll
                for (int rh = 0; rh < 2; rh++) {
                    int R = wm * 32 + mi * 16 + qr + rh * 8;
                    uint32_t off = (uint32_t)(C >> 6) * 8192 + (uint32_t)R * 128 +
                                   ((((uint32_t)(C & 63)) * 2) ^ ((R & 7) << 4));
                    uint32_t xh = *(uint32_t*)(sm3 + S3_XHI + off);
                    uint32_t xl = *(uint32_t*)(sm3 + S3_XLO + off);
                    float r0 = bflo_f(xh) + bflo_f(xl);
                    float r1 = bfhi_f(xh) + bfhi_f(xl);
                    outstage[R * OS_STRIDE + C]     = r0 + acc2[mi][nt][rh*2+0] + bC0;
                    outstage[R * OS_STRIDE + C + 1] = r1 + acc2[mi][nt][rh*2+1] + bC1;
                }
            }
        }
    }
    __syncthreads();

    // ---- LN2 ----
    #pragma unroll
    for (int k = 0; k < 8; k++) {
        int pp = wid * 8 + k;
        float v0 = outstage[pp*OS_STRIDE + lane];
        float v1 = outstage[pp*OS_STRIDE + lane + 32];
        float v2 = outstage[pp*OS_STRIDE + lane + 64];
        float v3 = outstage[pp*OS_STRIDE + lane + 96];
        float s  = wred(v0+v1+v2+v3);
        float s2 = wred(v0*v0+v1*v1+v2*v2+v3*v3);
        float mu = s * (1.f/128.f);
        float var = s2 * (1.f/128.f) - mu*mu;
        float rs = rsqrtf(var + 1e-5f);
        outstage[pp*OS_STRIDE + lane]      = (v0-mu)*rs*l2g[lane]    + l2b[lane];
        outstage[pp*OS_STRIDE + lane + 32] = (v1-mu)*rs*l2g[lane+32] + l2b[lane+32];
        outstage[pp*OS_STRIDE + lane + 64] = (v2-mu)*rs*l2g[lane+64] + l2b[lane+64];
        outstage[pp*OS_STRIDE + lane + 96] = (v3-mu)*rs*l2g[lane+96] + l2b[lane+96];
    }
    __syncthreads();

    // ---- transposed store ----
    for (int i = t; i < 64 * DDIM; i += 256) {
        int d = i >> 6, pp = i & 63;
        out[((size_t)b * DDIM + d) * PP + p0 + pp] = outstage[pp * OS_STRIDE + d];
    }
}

// ---------------------------------------------------------------------------
extern "C" void kernel_launch(void* const* d_in, const int* in_sizes, int n_in,
                              void* d_out, int out_size)
{
    const float* feature   = (const float*)d_in[0];
    const float* I_src     = (const float*)d_in[1];
    const float* I_tar_inv = (const float*)d_in[2];
    const float* E         = (const float*)d_in[3];
    const float* dis       = (const float*)d_in[4];
    const float* norm_vec  = (const float*)d_in[5];
    const float* bn_gamma  = (const float*)d_in[6];
    const float* bn_beta   = (const float*)d_in[7];
    const float* bn_mean   = (const float*)d_in[8];
    const float* bn_var    = (const float*)d_in[9];
    const float* conv_w    = (const float*)d_in[10];
    const float* ln1_g     = (const float*)d_in[11];
    const float* ln1_b     = (const float*)d_in[12];
    const float* mlp_w1    = (const float*)d_in[13];
    const float* mlp_b1    = (const float*)d_in[14];
    const float* mlp_w2    = (const float*)d_in[15];
    const float* mlp_b2    = (const float*)d_in[16];
    const float* ln2_g     = (const float*)d_in[17];
    const float* ln2_b     = (const float*)d_in[18];
    float* out = (float*)d_out;

    cudaFuncSetAttribute(k1_conv_tc,
                         cudaFuncAttributeMaxDynamicSharedMemorySize, K1_SMEM);
    cudaFuncSetAttribute(k3_mlp_tc,
                         cudaFuncAttributeMaxDynamicSharedMemorySize, K3T_SMEM);

    k0_prep<<<1, 256>>>(I_src, I_tar_inv, E, dis, norm_vec,
                        bn_gamma, bn_beta, bn_mean, bn_var);
    k0b1_pack<<<64, 256>>>(conv_w);
    k0b2_pack<<<64, 256>>>(mlp_w1, mlp_w2);
    k1_conv_tc<<<dim3(PP/128, BN), 512, K1_SMEM>>>(feature);
    k2_attn<<<dim3(PP/8, BB), 256>>>();
    k3_mlp_tc<<<dim3(PP/64, BB), 256, K3T_SMEM>>>(ln1_g, ln1_b, mlp_b1, mlp_b2,
                                                  ln2_g, ln2_b, out);
}

// round 17
// speedup vs baseline: 1.2130x; 1.0695x over previous
#include <cuda_runtime.h>
#include <cuda_bf16.h>
#include <math.h>
#include <stdint.h>

// Problem constants
#define BB 4
#define NN 6
#define FDIM 256
#define DDIM 128
#define HH 64
#define WW 120
#define PP (HH*WW)          // 7680
#define BN (BB*NN)          // 24
#define IMG_H 480.0f
#define IMG_W 960.0f

// Scratch (device globals — no runtime allocation allowed)
__device__ float g_val[(size_t)BN * PP * DDIM];   // (bn, p, d)  94.4 MB
__device__ float g_z[(size_t)BB * PP * DDIM];     // (b, p, d)   15.7 MB
__device__ float g_Hm[BN * 9];
__device__ float g_bnscale[FDIM];
__device__ float g_bnshift[FDIM];
// Prepacked split-bf16 weights
__device__ uint32_t g_wch[128 * 128];  // conv_w hi pairs [d][kpair]
__device__ uint32_t g_wcl[128 * 128];  // conv_w lo pairs
__device__ uint2 g_w1p[256 * 64];      // W1^T  [n=256][kpair=64]
__device__ uint2 g_w2p[128 * 128];     // W2^T  [n=128][kpair=128]

// ===========================================================================
// helpers: sm_80-baseline tensor path (ldmatrix + mma.sync) — no 'a' features
// ===========================================================================
__device__ __forceinline__ uint32_t smem_u32(const void* p) {
    uint32_t a;
    asm("{ .reg .u64 t; cvta.to.shared.u64 t, %1; cvt.u32.u64 %0, t; }"
        : "=r"(a) : "l"(p));
    return a;
}
__device__ __forceinline__ void ldsm_x4(uint32_t* r, uint32_t addr) {
    asm volatile("ldmatrix.sync.aligned.m8n8.x4.shared.b16 {%0,%1,%2,%3}, [%4];"
        : "=r"(r[0]), "=r"(r[1]), "=r"(r[2]), "=r"(r[3]) : "r"(addr));
}
__device__ __forceinline__ void mma_bf16(float* c, const uint32_t* a,
                                         uint32_t b0, uint32_t b1) {
    asm volatile(
        "mma.sync.aligned.m16n8k16.row.col.f32.bf16.bf16.f32 "
        "{%0,%1,%2,%3}, {%4,%5,%6,%7}, {%8,%9}, {%0,%1,%2,%3};"
        : "+f"(c[0]), "+f"(c[1]), "+f"(c[2]), "+f"(c[3])
        : "r"(a[0]), "r"(a[1]), "r"(a[2]), "r"(a[3]), "r"(b0), "r"(b1));
}
__device__ __forceinline__ void cp_async16(uint32_t smem_addr, const void* gptr) {
    asm volatile("cp.async.ca.shared.global [%0], [%1], 16;"
        :: "r"(smem_addr), "l"(gptr) : "memory");
}
__device__ __forceinline__ uint32_t pack_bf16x2(__nv_bfloat16 lo, __nv_bfloat16 hi) {
    return ((uint32_t)__bfloat16_as_ushort(hi) << 16) | __bfloat16_as_ushort(lo);
}
__device__ __forceinline__ uint2 split_pack(float a, float b) {
    __nv_bfloat16 ha = __float2bfloat16(a), hb = __float2bfloat16(b);
    __nv_bfloat16 la = __float2bfloat16(a - __bfloat162float(ha));
    __nv_bfloat16 lb = __float2bfloat16(b - __bfloat162float(hb));
    return make_uint2(pack_bf16x2(ha, hb), pack_bf16x2(la, lb));
}
__device__ __forceinline__ float bflo_f(uint32_t u) { return __uint_as_float(u << 16); }
__device__ __forceinline__ float bfhi_f(uint32_t u) { return __uint_as_float(u & 0xffff0000u); }
__device__ __forceinline__ float geluf(float h) {
    return 0.5f * h * (1.f + erff(h * 0.70710678118654752f));
}
__device__ __forceinline__ float wred(float v) {
    #pragma unroll
    for (int o = 16; o; o >>= 1) v += __shfl_xor_sync(0xffffffffu, v, o);
    return v;
}

// ---------------------------------------------------------------------------
// K0: homographies + BN scale/shift
// ---------------------------------------------------------------------------
__global__ void k0_prep(const float* __restrict__ I_src,
                        const float* __restrict__ I_tar_inv,
                        const float* __restrict__ E,
                        const float* __restrict__ disp,
                        const float* __restrict__ nvec,
                        const float* __restrict__ bng,
                        const float* __restrict__ bnb,
                        const float* __restrict__ bnm,
                        const float* __restrict__ bnv)
{
    int t = threadIdx.x;
    if (t < FDIM) {
        float sc = bng[t] * rsqrtf(bnv[t] + 1e-5f);
        g_bnscale[t] = sc;
        g_bnshift[t] = bnb[t] - bnm[t] * sc;
    }
    if (t < BN) {
        int b = t / NN;
        float dis = disp[0];
        const float* Eb = E + t * 16;
        const float* Ks = I_src + t * 9;
        const float* Kt = I_tar_inv + b * 9;
        float nv0 = nvec[b*3+0], nv1 = nvec[b*3+1], nv2 = nvec[b*3+2];
        float A[9];
        #pragma unroll
        for (int i = 0; i < 3; i++) {
            float Ti = Eb[i*4+3] / dis;
            A[i*3+0] = Eb[i*4+0] - Ti * nv0;
            A[i*3+1] = Eb[i*4+1] - Ti * nv1;
            A[i*3+2] = Eb[i*4+2] - Ti * nv2;
        }
        float M[9];
        #pragma unroll
        for (int i = 0; i < 3; i++)
            #pragma unroll
            for (int j = 0; j < 3; j++)
                M[i*3+j] = Ks[i*3+0]*A[0*3+j] + Ks[i*3+1]*A[1*3+j] + Ks[i*3+2]*A[2*3+j];
        #pragma unroll
        for (int i = 0; i < 3; i++)
            #pragma unroll
            for (int j = 0; j < 3; j++)
                g_Hm[t*9 + i*3+j] = M[i*3+0]*Kt[0*3+j] + M[i*3+1]*Kt[1*3+j] + M[i*3+2]*Kt[2*3+j];
    }
}

// ---------------------------------------------------------------------------
// K0b1: pack conv_w split-bf16 hi/lo pair arrays
// ---------------------------------------------------------------------------
__global__ void k0b1_pack(const float* __restrict__ Wc)
{
    int i = blockIdx.x * 256 + threadIdx.x;   // 0..16383
    int d = i >> 7, fp = i & 127;
    uint2 p = split_pack(Wc[d*256 + fp*2], Wc[d*256 + fp*2 + 1]);
    g_wch[i] = p.x;
    g_wcl[i] = p.y;
}

// ---------------------------------------------------------------------------
// K0b2: pack W1^T / W2^T split-bf16 pair arrays
// ---------------------------------------------------------------------------
__global__ void k0b2_pack(const float* __restrict__ W1,
                          const float* __restrict__ W2)
{
    int i = blockIdx.x * 256 + threadIdx.x;   // 0..16383
    {   // W2^T: g_w2p[n=d][kpair over j], W2 is [256 j][128 d]
        int d = i >> 7, kp = i & 127;
        g_w2p[i] = split_pack(W2[(kp*2)*128 + d], W2[(kp*2+1)*128 + d]);
    }
    {   // W1^T: g_w1p[n=j][kpair over d], W1 is [128 d][256 j]
        int j = i >> 6, kp = i & 63;
        g_w1p[i] = split_pack(W1[(kp*2)*256 + j], W1[(kp*2+1)*256 + j]);
    }
}

// ---------------------------------------------------------------------------
// K1 (HMMA, 512 threads / 16 warps, 2-stage pipelined, term-major):
// val[bn][p][d] = sum_f W[d][f]*relu(bn(feat))
// CTA tile 128px(M) x 128d(N), warp tile 32x32 (wm, wn in 0..3).
// ---------------------------------------------------------------------------
#define K1_SMEM 131072

__global__ void __launch_bounds__(512)
k1_conv_tc(const float* __restrict__ feat)
{
    extern __shared__ char smem[];
    const uint32_t sb = smem_u32(smem);
    const int bn = blockIdx.y;
    const int p0 = blockIdx.x * 128;
    const int t  = threadIdx.x;
    const int wid = t >> 5, lane = t & 31;
    const int wm = wid & 3;    // M quarter (rows wm*32..+31)
    const int wn = wid >> 2;   // N quarter (cols wn*32..+31)
    const int pl  = t & 127;   // X producer: pixel row
    const int fp0 = t >> 7;    // kpair phase 0..3

    float acc[2][4][4];
    #pragma unroll
    for (int mi = 0; mi < 2; mi++)
        #pragma unroll
        for (int nt = 0; nt < 4; nt++)
            #pragma unroll
            for (int j = 0; j < 4; j++) acc[mi][nt][j] = 0.f;

    const float* fb = feat + (size_t)bn * FDIM * PP + p0;

    // ---- prologue: stage 0 = chunk 0 ----
    #pragma unroll
    for (int i = 0; i < 2; i++) {           // W chunk 0 via cp.async
        int idx = t + i * 512;              // 16B-unit 0..1023
        int kq = idx & 7, dl = idx >> 3;
        uint32_t off = (uint32_t)dl * 128 + (((uint32_t)kq * 16) ^ ((dl & 7) << 4));
        cp_async16(sb + 65536 + off,          g_wch + dl * 128 + kq * 4);
        cp_async16(sb + 65536 + 16384 + off,  g_wcl + dl * 128 + kq * 4);
    }
    asm volatile("cp.async.commit_group;" ::: "memory");
    #pragma unroll
    for (int i = 0; i < 8; i++) {           // X chunk 0 direct
        int fp = fp0 + 4 * i;               // kpair 0..31
        int f  = 2 * fp;
        float v0 = fb[(size_t)f       * PP + pl];
        float v1 = fb[(size_t)(f + 1) * PP + pl];
        v0 = fmaxf(fmaf(v0, g_bnscale[f],   g_bnshift[f]),   0.f);
        v1 = fmaxf(fmaf(v1, g_bnscale[f+1], g_bnshift[f+1]), 0.f);
        uint2 p = split_pack(v0, v1);
        uint32_t off = (uint32_t)pl * 128 + (((uint32_t)fp * 4) ^ ((pl & 7) << 4));
        *(uint32_t*)(smem + off)         = p.x;
        *(uint32_t*)(smem + 16384 + off) = p.y;
    }

    for (int c = 0; c < 4; c++) {
        const int s = c & 1;
        const uint32_t xbase = sb + (uint32_t)s * 32768;
        const uint32_t wbase = sb + 65536 + (uint32_t)s * 32768;

        float v0r[8], v1r[8];
        if (c < 3) {
            const int f0n = (c + 1) * 64;
            #pragma unroll
            for (int i = 0; i < 8; i++) {
                int f = f0n + 2 * (fp0 + 4 * i);
                v0r[i] = fb[(size_t)f       * PP + pl];
                v1r[i] = fb[(size_t)(f + 1) * PP + pl];
            }
        }

        asm volatile("cp.async.wait_group 0;" ::: "memory");
        __syncthreads();

        if (c < 3) {
            const uint32_t wb1 = sb + 65536 + (uint32_t)(s ^ 1) * 32768;
            #pragma unroll
            for (int i = 0; i < 2; i++) {
                int idx = t + i * 512;
                int kq = idx & 7, dl = idx >> 3;
                uint32_t off = (uint32_t)dl * 128 + (((uint32_t)kq * 16) ^ ((dl & 7) << 4));
                cp_async16(wb1 + off,         g_wch + dl * 128 + (c + 1) * 32 + kq * 4);
                cp_async16(wb1 + 16384 + off, g_wcl + dl * 128 + (c + 1) * 32 + kq * 4);
            }
            asm volatile("cp.async.commit_group;" ::: "memory");
        }

        #pragma unroll
        for (int ks = 0; ks < 4; ks++) {
            const uint32_t kb = (uint32_t)ks * 32;
            uint32_t ah[2][4], al[2][4];
            #pragma unroll
            for (int mi = 0; mi < 2; mi++) {
                uint32_t row = (uint32_t)(wm * 32 + mi * 16 + (lane & 15));
                uint32_t kby = kb + ((lane >> 4) << 4);
                uint32_t off = row * 128 + (kby ^ ((row & 7) << 4));
                ldsm_x4(ah[mi], xbase + off);
                ldsm_x4(al[mi], xbase + 16384 + off);
            }
            uint32_t bh[2][4], bl[2][4];
            #pragma unroll
            for (int bj = 0; bj < 2; bj++) {
                uint32_t rown = (uint32_t)(wn * 32 + bj * 16 + (lane & 7) + ((lane >> 4) << 3));
                uint32_t kby  = kb + (((lane >> 3) & 1) << 4);
                uint32_t off  = rown * 128 + (kby ^ ((rown & 7) << 4));
                ldsm_x4(bh[bj], wbase + off);
                ldsm_x4(bl[bj], wbase + 16384 + off);
            }
            #pragma unroll
            for (int bj = 0; bj < 2; bj++)
                #pragma unroll
                for (int mi = 0; mi < 2; mi++) {
                    mma_bf16(acc[mi][bj*2+0], ah[mi], bh[bj][0], bh[bj][1]);
                    mma_bf16(acc[mi][bj*2+1], ah[mi], bh[bj][2], bh[bj][3]);
                }
            #pragma unroll
            for (int bj = 0; bj < 2; bj++)
                #pragma unroll
                for (int mi = 0; mi < 2; mi++) {
                    mma_bf16(acc[mi][bj*2+0], ah[mi], bl[bj][0], bl[bj][1]);
                    mma_bf16(acc[mi][bj*2+1], ah[mi], bl[bj][2], bl[bj][3]);
                }
            #pragma unroll
            for (int bj = 0; bj < 2; bj++)
                #pragma unroll
                for (int mi = 0; mi < 2; mi++) {
                    mma_bf16(acc[mi][bj*2+0], al[mi], bh[bj][0], bh[bj][1]);
                    mma_bf16(acc[mi][bj*2+1], al[mi], bh[bj][2], bh[bj][3]);
                }
        }

        if (c < 3) {
            const int f0n = (c + 1) * 64;
            char* xdst = smem + (size_t)(s ^ 1) * 32768;
            #pragma unroll
            for (int i = 0; i < 8; i++) {
                int fp = fp0 + 4 * i;
                int f  = f0n + 2 * fp;
                float v0 = fmaxf(fmaf(v0r[i], g_bnscale[f],   g_bnshift[f]),   0.f);
                float v1 = fmaxf(fmaf(v1r[i], g_bnscale[f+1], g_bnshift[f+1]), 0.f);
                uint2 p = split_pack(v0, v1);
                uint32_t off = (uint32_t)pl * 128 + (((uint32_t)fp * 4) ^ ((pl & 7) << 4));
                *(uint32_t*)(xdst + off)         = p.x;
                *(uint32_t*)(xdst + 16384 + off) = p.y;
            }
        }
    }

    const int qr = lane >> 2, qc = lane & 3;
    #pragma unroll
    for (int mi = 0; mi < 2; mi++) {
        int row0 = p0 + wm * 32 + mi * 16 + qr;
        float* r0 = g_val + ((size_t)bn * PP + row0) * DDIM;
        float* r1 = r0 + 8 * DDIM;
        #pragma unroll
        for (int nt = 0; nt < 4; nt++) {
            int col = wn * 32 + nt * 8 + qc * 2;
            *(float2*)(r0 + col) = make_float2(acc[mi][nt][0], acc[mi][nt][1]);
            *(float2*)(r1 + col) = make_float2(acc[mi][nt][2], acc[mi][nt][3]);
        }
    }
}

// ---------------------------------------------------------------------------
// K2: homography + bilinear sample + normalized dot + softmax + weighted sum
// ---------------------------------------------------------------------------
__global__ void __launch_bounds__(256) k2_attn()
{
    int b    = blockIdx.y;
    int p    = blockIdx.x * 8 + (threadIdx.x >> 5);
    int lane = threadIdx.x & 31;

    int col = p % WW, row = p / WW;
    float pxc = (float)col * (IMG_W / (float)(WW - 1));
    float pyc = (float)row * (IMG_H / (float)(HH - 1));

    const float4* qptr = (const float4*)(g_val + ((size_t)(b*NN + 0) * PP + p) * DDIM);
    float4 q4 = qptr[lane];
    float qss = wred(q4.x*q4.x + q4.y*q4.y + q4.z*q4.z + q4.w*q4.w);
    float qinv = 1.f / fmaxf(sqrtf(qss), 1e-12f);

    float4 s4[NN];
    float dotv[NN];

    #pragma unroll
    for (int n = 0; n < NN; n++) {
        const float* H = g_Hm + (b*NN + n) * 9;
        float hz = fmaf(H[6], pxc, fmaf(H[7], pyc, H[8]));
        float hx = fmaf(H[0], pxc, fmaf(H[1], pyc, H[2])) / hz;
        float hy = fmaf(H[3], pxc, fmaf(H[4], pyc, H[5])) / hz;
        float sx = hx * ((float)WW / IMG_W);
        float sy = hy * ((float)HH / IMG_H);
        bool valid = (sx >= 0.f) && (sx <= (float)(WW-1)) &&
                     (sy >= 0.f) && (sy <= (float)(HH-1));
        sx = fminf(fmaxf(sx, -1e4f), 1e4f);
        sy = fminf(fmaxf(sy, -1e4f), 1e4f);
        float x0f = floorf(sx), y0f = floorf(sy);
        int   x0 = (int)x0f,    y0 = (int)y0f;
        float fx = sx - x0f, fy = sy - y0f;

        float4 acc = make_float4(0.f, 0.f, 0.f, 0.f);
        const float* vb = g_val + (size_t)(b*NN + n) * PP * DDIM;
        #pragma unroll
        for (int c = 0; c < 4; c++) {
            int cx = x0 + (c & 1);
            int cy = y0 + (c >> 1);
            float wx = (c & 1)  ? fx : 1.f - fx;
            float wy = (c >> 1) ? fy : 1.f - fy;
            if (cx >= 0 && cx < WW && cy >= 0 && cy < HH) {
                const float4* vp = (const float4*)(vb + ((size_t)(cy*WW + cx)) * DDIM) + lane;
                float4 v = *vp;
                float w = wx * wy;
                acc.x = fmaf(w, v.x, acc.x);
                acc.y = fmaf(w, v.y, acc.y);
                acc.z = fmaf(w, v.z, acc.z);
                acc.w = fmaf(w, v.w, acc.w);
            }
        }
        s4[n] = acc;
        float ss = acc.x*acc.x + acc.y*acc.y + acc.z*acc.z + acc.w*acc.w;
        float dd = q4.x*acc.x + q4.y*acc.y + q4.z*acc.z + q4.w*acc.w;
        #pragma unroll
        for (int o = 16; o; o >>= 1) {
            ss += __shfl_xor_sync(0xffffffffu, ss, o);
            dd += __shfl_xor_sync(0xffffffffu, dd, o);
        }
        float sinv = 1.f / fmaxf(sqrtf(ss), 1e-12f);
        dotv[n] = valid ? dd * qinv * sinv : 0.f;
    }

    float m = dotv[0];
    #pragma unroll
    for (int n = 1; n < NN; n++) m = fmaxf(m, dotv[n]);
    float e[NN], se = 0.f;
    #pragma unroll
    for (int n = 0; n < NN; n++) { e[n] = expf(dotv[n] - m); se += e[n]; }
    float inv = 1.f / se;

    float4 o = q4;
    #pragma unroll
    for (int n = 0; n < NN; n++) {
        float a = e[n] * inv;
        o.x = fmaf(a, s4[n].x, o.x);
        o.y = fmaf(a, s4[n].y, o.y);
        o.z = fmaf(a, s4[n].z, o.z);
        o.w = fmaf(a, s4[n].w, o.w);
    }
    float4* zp = (float4*)(g_z + ((size_t)b * PP + p) * DDIM);
    zp[lane] = o;
}

// ---------------------------------------------------------------------------
// K3 (HMMA, 512 threads / 16 warps): LN1 -> GEMM1(64x256x128) -> gelu ->
// GEMM2(64x128x256) -> residual(LN1 out) -> LN2 -> transposed store
// GEMM1 warp tile 32x32 (wm=wid&1, wn=wid>>1); GEMM2 warp tile 32x16.
// ---------------------------------------------------------------------------
#define S3_XHI 0
#define S3_XLO 16384
#define S3_WHI 32768
#define S3_WLO 65536
#define S3_HHI 98304
#define S3_HLO 131072
#define K3T_SMEM 163840
#define OS_STRIDE 132

__global__ void __launch_bounds__(512)
k3_mlp_tc(const float* __restrict__ l1g, const float* __restrict__ l1b,
          const float* __restrict__ b1v, const float* __restrict__ b2v,
          const float* __restrict__ l2g, const float* __restrict__ l2b,
          float* __restrict__ out)
{
    extern __shared__ char sm3[];
    const uint32_t sb = smem_u32(sm3);
    const int b  = blockIdx.y;
    const int p0 = blockIdx.x * 64;
    const int t  = threadIdx.x;
    const int lane = t & 31, wid = t >> 5;   // wid 0..15

    // ---- Phase 0: load z, LN1, write X hi/lo tiles (4 rows per warp) ----
    {
        const float* zb = g_z + ((size_t)b * PP + p0) * DDIM;
        float4 g  = *(const float4*)(l1g + lane * 4);
        float4 be = *(const float4*)(l1b + lane * 4);
        #pragma unroll
        for (int rr = 0; rr < 4; rr++) {
            int row = wid * 4 + rr;
            float4 v = *(const float4*)(zb + (size_t)row * DDIM + lane * 4);
            float s  = wred(v.x + v.y + v.z + v.w);
            float s2 = wred(v.x*v.x + v.y*v.y + v.z*v.z + v.w*v.w);
            float mu = s * (1.f/128.f);
            float var = s2 * (1.f/128.f) - mu*mu;
            float rs = rsqrtf(var + 1e-5f);
            float x0 = (v.x - mu) * rs * g.x + be.x;
            float x1 = (v.y - mu) * rs * g.y + be.y;
            float x2 = (v.z - mu) * rs * g.z + be.z;
            float x3 = (v.w - mu) * rs * g.w + be.w;
            uint2 pA = split_pack(x0, x1);
            uint2 pB = split_pack(x2, x3);
            uint32_t base = (uint32_t)(lane >> 4) * 8192 + (uint32_t)row * 128;
            uint32_t o0 = base + ((((lane & 15) * 8) + 0) ^ ((row & 7) << 4));
            uint32_t o1 = base + ((((lane & 15) * 8) + 4) ^ ((row & 7) << 4));
            *(uint32_t*)(sm3 + S3_XHI + o0) = pA.x;
            *(uint32_t*)(sm3 + S3_XLO + o0) = pA.y;
            *(uint32_t*)(sm3 + S3_XHI + o1) = pB.x;
            *(uint32_t*)(sm3 + S3_XLO + o1) = pB.y;
        }
    }
    __syncthreads();

    const int wm = wid & 1;        // M half (32 rows)
    const int wn = wid >> 1;       // 0..7
    const int qr = lane >> 2, qc = lane & 3;

    // ---- GEMM1: H[64x256] = X[64x128] @ W1, warp tile 32x32 ----
    float acc[2][4][4];
    #pragma unroll
    for (int mi = 0; mi < 2; mi++)
        #pragma unroll
        for (int nt = 0; nt < 4; nt++)
            #pragma unroll
            for (int j = 0; j < 4; j++) acc[mi][nt][j] = 0.f;

    for (int kc = 0; kc < 2; kc++) {
        #pragma unroll 4
        for (int i = 0; i < 16; i++) {
            int idx = t + i * 512;
            int kpl = idx & 31, nl = idx >> 5;
            uint2 w = g_w1p[nl * 64 + kc * 32 + kpl];
            uint32_t off = (uint32_t)nl * 128 + (((uint32_t)kpl * 4) ^ ((nl & 7) << 4));
            *(uint32_t*)(sm3 + S3_WHI + off) = w.x;
            *(uint32_t*)(sm3 + S3_WLO + off) = w.y;
        }
        __syncthreads();

        #pragma unroll
        for (int ks = 0; ks < 4; ks++) {
            const uint32_t kb = (uint32_t)ks * 32;
            uint32_t ah[2][4], al[2][4];
            #pragma unroll
            for (int mi = 0; mi < 2; mi++) {
                uint32_t row = (uint32_t)(wm * 32 + mi * 16 + (lane & 15));
                uint32_t kby = kb + ((lane >> 4) << 4);
                uint32_t off = (uint32_t)kc * 8192 + row * 128 + (kby ^ ((row & 7) << 4));
                ldsm_x4(ah[mi], sb + S3_XHI + off);
                ldsm_x4(al[mi], sb + S3_XLO + off);
            }
            #pragma unroll
            for (int bj = 0; bj < 2; bj++) {
                uint32_t rown = (uint32_t)(wn * 32 + bj * 16 + (lane & 7) + ((lane >> 4) << 3));
                uint32_t kby  = kb + (((lane >> 3) & 1) << 4);
                uint32_t off  = rown * 128 + (kby ^ ((rown & 7) << 4));
                uint32_t bh[4], bl[4];
                ldsm_x4(bh, sb + S3_WHI + off);
                ldsm_x4(bl, sb + S3_WLO + off);
                #pragma unroll
                for (int mi = 0; mi < 2; mi++) {
                    mma_bf16(acc[mi][bj*2+0], ah[mi], bh[0], bh[1]);
                    mma_bf16(acc[mi][bj*2+0], ah[mi], bl[0], bl[1]);
                    mma_bf16(acc[mi][bj*2+0], al[mi], bh[0], bh[1]);
                    mma_bf16(acc[mi][bj*2+1], ah[mi], bh[2], bh[3]);
                    mma_bf16(acc[mi][bj*2+1], ah[mi], bl[2], bl[3]);
                    mma_bf16(acc[mi][bj*2+1], al[mi], bh[2], bh[3]);
                }
            }
        }
        __syncthreads();
    }

    // ---- gelu + write H tiles ----
    {
        #pragma unroll
        for (int mi = 0; mi < 2; mi++) {
            int R0 = wm * 32 + mi * 16 + qr;
            int R1 = R0 + 8;
            #pragma unroll
            for (int nt = 0; nt < 4; nt++) {
                int C = wn * 32 + nt * 8 + qc * 2;     // 0..255
                float h00 = geluf(acc[mi][nt][0] + b1v[C]);
                float h01 = geluf(acc[mi][nt][1] + b1v[C+1]);
                float h10 = geluf(acc[mi][nt][2] + b1v[C]);
                float h11 = geluf(acc[mi][nt][3] + b1v[C+1]);
                uint2 pA = split_pack(h00, h01);
                uint2 pB = split_pack(h10, h11);
                uint32_t base = (uint32_t)(C >> 6) * 8192;
                uint32_t kloc = (uint32_t)(C & 63) * 2;
                uint32_t oA = base + (uint32_t)R0 * 128 + (kloc ^ ((R0 & 7) << 4));
                uint32_t oB = base + (uint32_t)R1 * 128 + (kloc ^ ((R1 & 7) << 4));
                *(uint32_t*)(sm3 + S3_HHI + oA) = pA.x;
                *(uint32_t*)(sm3 + S3_HLO + oA) = pA.y;
                *(uint32_t*)(sm3 + S3_HHI + oB) = pB.x;
                *(uint32_t*)(sm3 + S3_HLO + oB) = pB.y;
            }
        }
    }
    __syncthreads();

    // ---- GEMM2: O[64x128] = H[64x256] @ W2, warp tile 32x16 ----
    float acc2[2][2][4];
    #pragma unroll
    for (int mi = 0; mi < 2; mi++)
        #pragma unroll
        for (int nt = 0; nt < 2; nt++)
            #pragma unroll
            for (int j = 0; j < 4; j++) acc2[mi][nt][j] = 0.f;

    for (int kc = 0; kc < 4; kc++) {
        #pragma unroll 4
        for (int i = 0; i < 8; i++) {
            int idx = t + i * 512;
            int kpl = idx & 31, nl = idx >> 5;
            uint2 w = g_w2p[nl * 128 + kc * 32 + kpl];
            uint32_t off = (uint32_t)nl * 128 + (((uint32_t)kpl * 4) ^ ((nl & 7) << 4));
            *(uint32_t*)(sm3 + S3_WHI + off) = w.x;
            *(uint32_t*)(sm3 + S3_WLO + off) = w.y;
        }
        __syncthreads();

        #pragma unroll
        for (int ks = 0; ks < 4; ks++) {
            const uint32_t kb = (uint32_t)ks * 32;
            uint32_t ah[2][4], al[2][4];
            #pragma unroll
            for (int mi = 0; mi < 2; mi++) {
                uint32_t row = (uint32_t)(wm * 32 + mi * 16 + (lane & 15));
                uint32_t kby = kb + ((lane >> 4) << 4);
                uint32_t off = (uint32_t)kc * 8192 + row * 128 + (kby ^ ((row & 7) << 4));
                ldsm_x4(ah[mi], sb + S3_HHI + off);
                ldsm_x4(al[mi], sb + S3_HLO + off);
            }
            {
                uint32_t rown = (uint32_t)(wn * 16 + (lane & 7) + ((lane >> 4) << 3));
                uint32_t kby  = kb + (((lane >> 3) & 1) << 4);
                uint32_t off  = rown * 128 + (kby ^ ((rown & 7) << 4));
                uint32_t bh[4], bl[4];
                ldsm_x4(bh, sb + S3_WHI + off);
                ldsm_x4(bl, sb + S3_WLO + off);
                #pragma unroll
                for (int mi = 0; mi < 2; mi++) {
                    mma_bf16(acc2[mi][0], ah[mi], bh[0], bh[1]);
                    mma_bf16(acc2[mi][0], ah[mi], bl[0], bl[1]);
                    mma_bf16(acc2[mi][0], al[mi], bh[0], bh[1]);
                    mma_bf16(acc2[mi][1], ah[mi], bh[2], bh[3]);
                    mma_bf16(acc2[mi][1], ah[mi], bl[2], bl[3]);
                    mma_bf16(acc2[mi][1], al[mi], bh[2], bh[3]);
                }
            }
        }
        __syncthreads();
    }

    // ---- epilogue: residual + bias ----
    float* outstage = (float*)(sm3 + S3_WHI);
    {
        #pragma unroll
        for (int mi = 0; mi < 2; mi++) {
            #pragma unroll
            for (int nt = 0; nt < 2; nt++) {
                int C = wn * 16 + nt * 8 + qc * 2;    // 0..127
                float bC0 = b2v[C], bC1 = b2v[C+1];
                #pragma unroll
                for (int rh = 0; rh < 2; rh++) {
                    int R = wm * 32 + mi * 16 + qr + rh * 8;
                    uint32_t off = (uint32_t)(C >> 6) * 8192 + (uint32_t)R * 128 +
                                   ((((uint32_t)(C & 63)) * 2) ^ ((R & 7) << 4));
                    uint32_t xh = *(uint32_t*)(sm3 + S3_XHI + off);
                    uint32_t xl = *(uint32_t*)(sm3 + S3_XLO + off);
                    float r0 = bflo_f(xh) + bflo_f(xl);
                    float r1 = bfhi_f(xh) + bfhi_f(xl);
                    outstage[R * OS_STRIDE + C]     = r0 + acc2[mi][nt][rh*2+0] + bC0;
                    outstage[R * OS_STRIDE + C + 1] = r1 + acc2[mi][nt][rh*2+1] + bC1;
                }
            }
        }
    }
    __syncthreads();

    // ---- LN2 (4 rows per warp) ----
    #pragma unroll
    for (int k = 0; k < 4; k++) {
        int pp = wid * 4 + k;
        float v0 = outstage[pp*OS_STRIDE + lane];
        float v1 = outstage[pp*OS_STRIDE + lane + 32];
        float v2 = outstage[pp*OS_STRIDE + lane + 64];
        float v3 = outstage[pp*OS_STRIDE + lane + 96];
        float s  = wred(v0+v1+v2+v3);
        float s2 = wred(v0*v0+v1*v1+v2*v2+v3*v3);
        float mu = s * (1.f/128.f);
        float var = s2 * (1.f/128.f) - mu*mu;
        float rs = rsqrtf(var + 1e-5f);
        outstage[pp*OS_STRIDE + lane]      = (v0-mu)*rs*l2g[lane]    + l2b[lane];
        outstage[pp*OS_STRIDE + lane + 32] = (v1-mu)*rs*l2g[lane+32] + l2b[lane+32];
        outstage[pp*OS_STRIDE + lane + 64] = (v2-mu)*rs*l2g[lane+64] + l2b[lane+64];
        outstage[pp*OS_STRIDE + lane + 96] = (v3-mu)*rs*l2g[lane+96] + l2b[lane+96];
    }
    __syncthreads();

    // ---- transposed store ----
    for (int i = t; i < 64 * DDIM; i += 512) {
        int d = i >> 6, pp = i & 63;
        out[((size_t)b * DDIM + d) * PP + p0 + pp] = outstage[pp * OS_STRIDE + d];
    }
}

// ---------------------------------------------------------------------------
extern "C" void kernel_launch(void* const* d_in, const int* in_sizes, int n_in,
                              void* d_out, int out_size)
{
    const float* feature   = (const float*)d_in[0];
    const float* I_src     = (const float*)d_in[1];
    const float* I_tar_inv = (const float*)d_in[2];
    const float* E         = (const float*)d_in[3];
    const float* dis       = (const float*)d_in[4];
    const float* norm_vec  = (const float*)d_in[5];
    const float* bn_gamma  = (const float*)d_in[6];
    const float* bn_beta   = (const float*)d_in[7];
    const float* bn_mean   = (const float*)d_in[8];
    const float* bn_var    = (const float*)d_in[9];
    const float* conv_w    = (const float*)d_in[10];
    const float* ln1_g     = (const float*)d_in[11];
    const float* ln1_b     = (const float*)d_in[12];
    const float* mlp_w1    = (const float*)d_in[13];
    const float* mlp_b1    = (const float*)d_in[14];
    const float* mlp_w2    = (const float*)d_in[15];
    const float* mlp_b2    = (const float*)d_in[16];
    const float* ln2_g     = (const float*)d_in[17];
    const float* ln2_b     = (const float*)d_in[18];
    float* out = (float*)d_out;

    cudaFuncSetAttribute(k1_conv_tc,
                         cudaFuncAttributeMaxDynamicSharedMemorySize, K1_SMEM);
    cudaFuncSetAttribute(k3_mlp_tc,
                         cudaFuncAttributeMaxDynamicSharedMemorySize, K3T_SMEM);

    k0_prep<<<1, 256>>>(I_src, I_tar_inv, E, dis, norm_vec,
                        bn_gamma, bn_beta, bn_mean, bn_var);
    k0b1_pack<<<64, 256>>>(conv_w);
    k0b2_pack<<<64, 256>>>(mlp_w1, mlp_w2);
    k1_conv_tc<<<dim3(PP/128, BN), 512, K1_SMEM>>>(feature);
    k2_attn<<<dim3(PP/8, BB), 256>>>();
    k3_mlp_tc<<<dim3(PP/64, BB), 512, K3T_SMEM>>>(ln1_g, ln1_b, mlp_b1, mlp_b2,
                                                  ln2_g, ln2_b, out);
}